// round 9
// baseline (speedup 1.0000x reference)
#include <cuda_runtime.h>
#include <math_constants.h>

#define BATCH  4
#define NPTS   4096
#define NQ     (BATCH * NPTS)   // 16384
#define KNN    16
#define NROWS  (NQ * KNN)       // 262144
#define C2     128
#define EPSBN  1e-5f

#define TAU_SLICES   8
#define TAU_SLICE_N  64
#define COL_SLICES   8
#define COL_SLICE_N  512
#define COL_CAP      64

// ---------------- scratch (no device allocations allowed) ----------------
__device__ float4 g_pack[NQ];
__device__ int    g_idx[NROWS];
__device__ float  g_P0[NQ * 64];
__device__ float  g_sd[NQ * 128];
__device__ float  g_tau[NQ];
__device__ float  g_cd[(size_t)NQ * COL_SLICES * COL_CAP];
__device__ int    g_ci[(size_t)NQ * COL_SLICES * COL_CAP];
__device__ int    g_cnt[NQ * COL_SLICES];
__device__ float  g_H1[(size_t)NROWS * 64];

// ---------------- helpers ----------------
__device__ __forceinline__ float fold_scale(float g, float rv) {
    float v = rv + EPSBN;
    float r = rsqrtf(v);
    r = r * (1.5f - 0.5f * v * r * r);
    return g * r;
}

__device__ __forceinline__ float dist2f(float qx, float qy, float qz, float qsq, float4 p) {
    float dot = fmaf(qz, p.z, fmaf(qy, p.y, __fmul_rn(qx, p.x)));
    return __fadd_rn(__fadd_rn(qsq, p.w), __fmul_rn(-2.0f, dot));
}

__device__ __forceinline__ void ins_v(float dd, float* d, float& wmax) {
    bool done = false;
#pragma unroll
    for (int i = 0; i < KNN; i++) {
        bool m = (!done) && (d[i] == wmax);
        if (m) d[i] = dd;
        done = done || m;
    }
    wmax = d[0];
#pragma unroll
    for (int i = 1; i < KNN; i++) wmax = fmaxf(wmax, d[i]);
}

// ---- packed f32x2 primitives (FFMA2 only reachable via PTX) ----
__device__ __forceinline__ unsigned long long f32x2_pack(float lo, float hi) {
    unsigned long long r;
    asm("mov.b64 %0, {%1, %2};" : "=l"(r) : "f"(lo), "f"(hi));
    return r;
}
__device__ __forceinline__ void f32x2_unpack(unsigned long long v, float& lo, float& hi) {
    asm("mov.b64 {%0, %1}, %2;" : "=f"(lo), "=f"(hi) : "l"(v));
}
__device__ __forceinline__ void ffma2(unsigned long long& d,
                                      unsigned long long a, unsigned long long b) {
    asm("fma.rn.f32x2 %0, %1, %2, %0;" : "+l"(d) : "l"(a), "l"(b));
}

// ---------------- kernel 1: pack xyz + squared norm ----------------
__global__ void pack_kernel(const float* __restrict__ xyz) {
    int i = blockIdx.x * blockDim.x + threadIdx.x;
    if (i < NQ) {
        float x = xyz[3 * i + 0];
        float y = xyz[3 * i + 1];
        float z = xyz[3 * i + 2];
        float sq = fmaf(z, z, fmaf(y, y, __fmul_rn(x, x)));
        g_pack[i] = make_float4(x, y, z, sq);
    }
}

// ---------------- kernel 2: P0 ----------------
__global__ void __launch_bounds__(256) p0_kernel(const float* __restrict__ points,
                                                 const float* __restrict__ w0,
                                                 const float* __restrict__ g0,
                                                 const float* __restrict__ rv0) {
    __shared__ float w0f[64][64];
    int tid = threadIdx.x;
    for (int e = tid; e < 4096; e += 256) {
        int o = e & 63, c = e >> 6;
        float s = fold_scale(g0[o], rv0[o]);
        w0f[c][o] = w0[o * 67 + 3 + c] * s;
    }
    __syncthreads();

    int o     = tid & 63;
    int jl    = tid >> 6;
    int jbase = blockIdx.x * 64;
#pragma unroll 1
    for (int t = 0; t < 16; t++) {
        int j = jbase + jl + (t << 2);
        const float4* prow = (const float4*)(points + (size_t)j * 64);
        float acc = 0.0f;
#pragma unroll
        for (int c4 = 0; c4 < 16; c4++) {
            float4 p = prow[c4];
            acc = fmaf(p.x, w0f[c4 * 4 + 0][o], acc);
            acc = fmaf(p.y, w0f[c4 * 4 + 1][o], acc);
            acc = fmaf(p.z, w0f[c4 * 4 + 2][o], acc);
            acc = fmaf(p.w, w0f[c4 * 4 + 3][o], acc);
        }
        g_P0[(size_t)j * 64 + o] = acc;
    }
}

// ---------------- kernel 3a: tauA ----------------
__global__ void __launch_bounds__(128) tauA_kernel() {
    int q = blockIdx.x * 128 + threadIdx.x;
    int s = blockIdx.y;
    int base  = (q >> 12) << 12;
    int cbase = base + s * TAU_SLICE_N;
    const float4* __restrict__ cand = g_pack + cbase;

    float4 me = g_pack[q];
    float qx = me.x, qy = me.y, qz = me.z, qsq = me.w;

    float d[KNN];
#pragma unroll
    for (int i = 0; i < KNN; i++) d[i] = CUDART_INF_F;
    float wmax = CUDART_INF_F;

    for (int c = 0; c < TAU_SLICE_N; c += 4) {
        float dd0 = dist2f(qx, qy, qz, qsq, cand[c + 0]);
        float dd1 = dist2f(qx, qy, qz, qsq, cand[c + 1]);
        float dd2 = dist2f(qx, qy, qz, qsq, cand[c + 2]);
        float dd3 = dist2f(qx, qy, qz, qsq, cand[c + 3]);
        if (dd0 < wmax) ins_v(dd0, d, wmax);
        if (dd1 < wmax) ins_v(dd1, d, wmax);
        if (dd2 < wmax) ins_v(dd2, d, wmax);
        if (dd3 < wmax) ins_v(dd3, d, wmax);
    }

#pragma unroll
    for (int i = 0; i < KNN; i++) g_sd[(size_t)q * 128 + s * KNN + i] = d[i];
}

// ---------------- kernel 3b: tauB ----------------
__global__ void __launch_bounds__(128) tauB_kernel() {
    int lane = threadIdx.x & 31;
    int q = blockIdx.x * 4 + (threadIdx.x >> 5);

    float4 v4 = *(const float4*)(g_sd + (size_t)q * 128 + lane * 4);
    float v0 = v4.x, v1 = v4.y, v2 = v4.z, v3 = v4.w;

    float tau = CUDART_INF_F;
#pragma unroll
    for (int it = 0; it < KNN; it++) {
        float m = fminf(fminf(v0, v1), fminf(v2, v3));
#pragma unroll
        for (int off = 16; off; off >>= 1)
            m = fminf(m, __shfl_xor_sync(0xFFFFFFFFu, m, off));
        if (v0 == m) v0 = CUDART_INF_F;
        if (v1 == m) v1 = CUDART_INF_F;
        if (v2 == m) v2 = CUDART_INF_F;
        if (v3 == m) v3 = CUDART_INF_F;
        tau = m;
    }
    if (lane == 0) g_tau[q] = tau;
}

// ---------------- kernel 3c: collect ----------------
__global__ void __launch_bounds__(128) collect_kernel() {
    int q = blockIdx.x * 128 + threadIdx.x;
    int s = blockIdx.y;
    int base  = (q >> 12) << 12;
    int cbase = base + s * COL_SLICE_N;
    const float4* __restrict__ cand = g_pack + cbase;

    float4 me = g_pack[q];
    float qx = me.x, qy = me.y, qz = me.z, qsq = me.w;
    float tau = g_tau[q];

    size_t obase = ((size_t)q * COL_SLICES + s) * COL_CAP;
    int cnt = 0;

    for (int c = 0; c < COL_SLICE_N; c += 4) {
        float dd0 = dist2f(qx, qy, qz, qsq, cand[c + 0]);
        float dd1 = dist2f(qx, qy, qz, qsq, cand[c + 1]);
        float dd2 = dist2f(qx, qy, qz, qsq, cand[c + 2]);
        float dd3 = dist2f(qx, qy, qz, qsq, cand[c + 3]);
        if (dd0 <= tau && cnt < COL_CAP) { g_cd[obase + cnt] = dd0; g_ci[obase + cnt] = cbase + c + 0; cnt++; }
        if (dd1 <= tau && cnt < COL_CAP) { g_cd[obase + cnt] = dd1; g_ci[obase + cnt] = cbase + c + 1; cnt++; }
        if (dd2 <= tau && cnt < COL_CAP) { g_cd[obase + cnt] = dd2; g_ci[obase + cnt] = cbase + c + 2; cnt++; }
        if (dd3 <= tau && cnt < COL_CAP) { g_cd[obase + cnt] = dd3; g_ci[obase + cnt] = cbase + c + 3; cnt++; }
    }
    g_cnt[q * COL_SLICES + s] = cnt;
}

// ---------------- kernel 3d: select ----------------
__global__ void __launch_bounds__(128) select_kernel() {
    int lane = threadIdx.x & 31;
    int q = blockIdx.x * 4 + (threadIdx.x >> 5);

    int cnt = (lane < COL_SLICES) ? g_cnt[q * COL_SLICES + lane] : 0;
    int pre = cnt;
#pragma unroll
    for (int off = 1; off < 8; off <<= 1) {
        int n = __shfl_up_sync(0xFFFFFFFFu, pre, off);
        if (lane >= off) pre += n;
    }
    int p0 = __shfl_sync(0xFFFFFFFFu, pre, 0);
    int p1 = __shfl_sync(0xFFFFFFFFu, pre, 1);
    int p2 = __shfl_sync(0xFFFFFFFFu, pre, 2);
    int p3 = __shfl_sync(0xFFFFFFFFu, pre, 3);
    int p4 = __shfl_sync(0xFFFFFFFFu, pre, 4);
    int p5 = __shfl_sync(0xFFFFFFFFu, pre, 5);
    int p6 = __shfl_sync(0xFFFFFFFFu, pre, 6);
    int total = __shfl_sync(0xFFFFFFFFu, pre, 7);

    unsigned long long key[16];
#pragma unroll
    for (int g = 0; g < 16; g++) {
        key[g] = ~0ull;
        int e = lane + (g << 5);
        if (e < total) {
            int s = (e >= p0) + (e >= p1) + (e >= p2) + (e >= p3)
                  + (e >= p4) + (e >= p5) + (e >= p6);
            int start = 0;
            if (s > 0) start = p0;
            if (s > 1) start = p1;
            if (s > 2) start = p2;
            if (s > 3) start = p3;
            if (s > 4) start = p4;
            if (s > 5) start = p5;
            if (s > 6) start = p6;
            size_t off = ((size_t)q * COL_SLICES + s) * COL_CAP + (e - start);
            float d  = g_cd[off];
            int   ci = g_ci[off];
            unsigned u = __float_as_uint(d);
            u = ((int)u < 0) ? ~u : (u | 0x80000000u);
            key[g] = ((unsigned long long)u << 32) | (unsigned)ci;
        }
    }

#pragma unroll 1
    for (int it = 0; it < KNN; it++) {
        unsigned long long m = key[0];
#pragma unroll
        for (int i = 1; i < 16; i++) m = (key[i] < m) ? key[i] : m;
#pragma unroll
        for (int off = 16; off; off >>= 1) {
            unsigned long long o = __shfl_xor_sync(0xFFFFFFFFu, m, off);
            m = (o < m) ? o : m;
        }
#pragma unroll
        for (int i = 0; i < 16; i++)
            if (key[i] == m) key[i] = ~0ull;
        if (lane == 0) g_idx[q * KNN + it] = (int)(m & 0xFFFFFFFFu);
    }
}

// ---------------- kernel 4a: layer0 + layer1 -> g_H1 (FFMA2) ----------------
__global__ void __launch_bounds__(128) mlp1_kernel(
    const float* __restrict__ w0, const float* __restrict__ b0,
    const float* __restrict__ g0, const float* __restrict__ be0,
    const float* __restrict__ rm0, const float* __restrict__ rv0,
    const float* __restrict__ w1, const float* __restrict__ b1,
    const float* __restrict__ g1, const float* __restrict__ be1,
    const float* __restrict__ rm1, const float* __restrict__ rv1)
{
    __shared__ __align__(16) float4 W0B[64];
    __shared__ __align__(16) float  W1S[4096];   // [c][o] folded (c-major -> o-pairs adjacent)
    __shared__ float  B1F[64];
    __shared__ float  S1[64];

    int tid = threadIdx.x;
    if (tid < 64) {
        float s0 = fold_scale(g0[tid], rv0[tid]);
        W0B[tid] = make_float4(w0[tid * 67 + 0] * s0,
                               w0[tid * 67 + 1] * s0,
                               w0[tid * 67 + 2] * s0,
                               (b0[tid] - rm0[tid]) * s0 + be0[tid]);
        float s1v = fold_scale(g1[tid], rv1[tid]);
        S1[tid]  = s1v;
        B1F[tid] = (b1[tid] - rm1[tid]) * s1v + be1[tid];
    }
    __syncthreads();
    for (int e = tid; e < 4096; e += 128) {
        int c = e >> 6, o = e & 63;
        W1S[e] = w1[o * 64 + c] * S1[o];
    }
    __syncthreads();

    int row = blockIdx.x * 128 + tid;
    int q   = row >> 4;
    int j   = g_idx[row];

    float4 pj = g_pack[j];
    float4 pq = g_pack[q];
    float rx = pj.x - pq.x, ry = pj.y - pq.y, rz = pj.z - pq.z;

    // layer 0
    float h0[64];
    const float4* p0row = (const float4*)(g_P0 + (size_t)j * 64);
#pragma unroll
    for (int o4 = 0; o4 < 16; o4++) {
        float4 p = p0row[o4];
        float pv[4] = { p.x, p.y, p.z, p.w };
#pragma unroll
        for (int u = 0; u < 4; u++) {
            int o = o4 * 4 + u;
            float4 w = W0B[o];
            float v = fmaf(w.x, rx, fmaf(w.y, ry, fmaf(w.z, rz, pv[u] + w.w)));
            h0[o] = fmaxf(v, 0.0f);
        }
    }

    // layer 1: 4 passes x 16 outputs, packed f32x2 accumulators
    float4* hout = (float4*)(g_H1 + (size_t)row * 64);
#pragma unroll 1
    for (int og = 0; og < 4; og++) {
        unsigned long long a[8];
#pragma unroll
        for (int p = 0; p < 8; p++)
            a[p] = f32x2_pack(B1F[og * 16 + 2 * p], B1F[og * 16 + 2 * p + 1]);
#pragma unroll
        for (int c = 0; c < 64; c++) {
            unsigned long long hs = f32x2_pack(h0[c], h0[c]);
            const ulonglong2* wv = (const ulonglong2*)(W1S + c * 64 + og * 16);
            ulonglong2 wA = wv[0], wB = wv[1], wC = wv[2], wD = wv[3];
            ffma2(a[0], wA.x, hs); ffma2(a[1], wA.y, hs);
            ffma2(a[2], wB.x, hs); ffma2(a[3], wB.y, hs);
            ffma2(a[4], wC.x, hs); ffma2(a[5], wC.y, hs);
            ffma2(a[6], wD.x, hs); ffma2(a[7], wD.y, hs);
        }
#pragma unroll
        for (int p = 0; p < 4; p++) {
            float l0, h0v, l1, h1v;
            f32x2_unpack(a[2 * p],     l0, h0v);
            f32x2_unpack(a[2 * p + 1], l1, h1v);
            hout[og * 4 + p] = make_float4(fmaxf(l0, 0.0f), fmaxf(h0v, 0.0f),
                                           fmaxf(l1, 0.0f), fmaxf(h1v, 0.0f));
        }
    }
}

// ---------------- kernel 4b: layer2 + maxpool (FFMA2) ----------------
__global__ void __launch_bounds__(128) mlp2_kernel(
    const float* __restrict__ w2, const float* __restrict__ b2,
    const float* __restrict__ g2, const float* __restrict__ be2,
    const float* __restrict__ rm2, const float* __restrict__ rv2,
    float* __restrict__ out)
{
    __shared__ __align__(16) float W2S[8192];    // [c][o] folded
    __shared__ float B2F[128];
    __shared__ float S2[128];

    int tid = threadIdx.x;
    {
        float s2v = fold_scale(g2[tid], rv2[tid]);
        S2[tid]  = s2v;
        B2F[tid] = (b2[tid] - rm2[tid]) * s2v + be2[tid];
    }
    __syncthreads();
    for (int e = tid; e < 8192; e += 128) {
        int c = e >> 7, o = e & 127;
        W2S[e] = w2[o * 64 + c] * S2[o];
    }
    __syncthreads();

    int row  = blockIdx.x * 128 + tid;
    int q    = row >> 4;
    int lane = tid & 31;

    float h1[64];
    const float4* hin = (const float4*)(g_H1 + (size_t)row * 64);
#pragma unroll
    for (int c4 = 0; c4 < 16; c4++) {
        float4 h = hin[c4];
        h1[c4 * 4 + 0] = h.x; h1[c4 * 4 + 1] = h.y;
        h1[c4 * 4 + 2] = h.z; h1[c4 * 4 + 3] = h.w;
    }

    float* orow = out + (size_t)q * C2;
#pragma unroll 1
    for (int og = 0; og < 8; og++) {
        unsigned long long a[8];
#pragma unroll
        for (int p = 0; p < 8; p++)
            a[p] = f32x2_pack(B2F[og * 16 + 2 * p], B2F[og * 16 + 2 * p + 1]);
#pragma unroll
        for (int c = 0; c < 64; c++) {
            unsigned long long hs = f32x2_pack(h1[c], h1[c]);
            const ulonglong2* wv = (const ulonglong2*)(W2S + c * 128 + og * 16);
            ulonglong2 wA = wv[0], wB = wv[1], wC = wv[2], wD = wv[3];
            ffma2(a[0], wA.x, hs); ffma2(a[1], wA.y, hs);
            ffma2(a[2], wB.x, hs); ffma2(a[3], wB.y, hs);
            ffma2(a[4], wC.x, hs); ffma2(a[5], wC.y, hs);
            ffma2(a[6], wD.x, hs); ffma2(a[7], wD.y, hs);
        }
#pragma unroll
        for (int p = 0; p < 8; p++) {
            float lo, hi;
            f32x2_unpack(a[p], lo, hi);
            lo = fmaxf(lo, 0.0f);
            hi = fmaxf(hi, 0.0f);
#pragma unroll
            for (int off = 1; off < 16; off <<= 1) {
                lo = fmaxf(lo, __shfl_xor_sync(0xFFFFFFFFu, lo, off));
                hi = fmaxf(hi, __shfl_xor_sync(0xFFFFFFFFu, hi, off));
            }
            if ((lane & 15) == 0)
                *(float2*)(orow + og * 16 + 2 * p) = make_float2(lo, hi);
        }
    }
}

// ---------------- launch ----------------
extern "C" void kernel_launch(void* const* d_in, const int* in_sizes, int n_in,
                              void* d_out, int out_size) {
    (void)in_sizes; (void)n_in; (void)out_size;
    const float* xyz    = (const float*)d_in[0];
    const float* points = (const float*)d_in[1];
    const float* w0  = (const float*)d_in[2];
    const float* b0  = (const float*)d_in[3];
    const float* g0  = (const float*)d_in[4];
    const float* be0 = (const float*)d_in[5];
    const float* rm0 = (const float*)d_in[6];
    const float* rv0 = (const float*)d_in[7];
    const float* w1  = (const float*)d_in[8];
    const float* b1  = (const float*)d_in[9];
    const float* g1  = (const float*)d_in[10];
    const float* be1 = (const float*)d_in[11];
    const float* rm1 = (const float*)d_in[12];
    const float* rv1 = (const float*)d_in[13];
    const float* w2  = (const float*)d_in[14];
    const float* b2  = (const float*)d_in[15];
    const float* g2  = (const float*)d_in[16];
    const float* be2 = (const float*)d_in[17];
    const float* rm2 = (const float*)d_in[18];
    const float* rv2 = (const float*)d_in[19];
    float* out = (float*)d_out;

    pack_kernel<<<NQ / 256, 256>>>(xyz);
    p0_kernel<<<NQ / 64, 256>>>(points, w0, g0, rv0);
    tauA_kernel<<<dim3(NQ / 128, TAU_SLICES), 128>>>();
    tauB_kernel<<<NQ / 4, 128>>>();
    collect_kernel<<<dim3(NQ / 128, COL_SLICES), 128>>>();
    select_kernel<<<NQ / 4, 128>>>();
    mlp1_kernel<<<NROWS / 128, 128>>>(w0, b0, g0, be0, rm0, rv0,
                                      w1, b1, g1, be1, rm1, rv1);
    mlp2_kernel<<<NROWS / 128, 128>>>(w2, b2, g2, be2, rm2, rv2, out);
}

// round 10
// speedup vs baseline: 1.1694x; 1.1694x over previous
#include <cuda_runtime.h>
#include <math_constants.h>

#define BATCH  4
#define NPTS   4096
#define NQ     (BATCH * NPTS)   // 16384
#define KNN    16
#define NROWS  (NQ * KNN)       // 262144
#define C2     128
#define EPSBN  1e-5f

#define TAU_SLICES   8
#define TAU_SLICE_N  64
#define COL_SLICES   8
#define COL_SLICE_N  512
#define COL_CAP      64

// ---------------- scratch (no device allocations allowed) ----------------
__device__ float4 g_pack[NQ];
__device__ int    g_idx[NROWS];
__device__ float  g_P0[NQ * 64];
__device__ float  g_sd[NQ * 128];
__device__ float  g_tau[NQ];
__device__ float  g_cd[(size_t)NQ * COL_SLICES * COL_CAP];
__device__ int    g_ci[(size_t)NQ * COL_SLICES * COL_CAP];
__device__ int    g_cnt[NQ * COL_SLICES];

// ---------------- helpers ----------------
__device__ __forceinline__ float fold_scale(float g, float rv) {
    float v = rv + EPSBN;
    float r = rsqrtf(v);
    r = r * (1.5f - 0.5f * v * r * r);
    return g * r;
}

__device__ __forceinline__ float dist2f(float qx, float qy, float qz, float qsq, float4 p) {
    float dot = fmaf(qz, p.z, fmaf(qy, p.y, __fmul_rn(qx, p.x)));
    return __fadd_rn(__fadd_rn(qsq, p.w), __fmul_rn(-2.0f, dot));
}

__device__ __forceinline__ void ins_v(float dd, float* d, float& wmax) {
    bool done = false;
#pragma unroll
    for (int i = 0; i < KNN; i++) {
        bool m = (!done) && (d[i] == wmax);
        if (m) d[i] = dd;
        done = done || m;
    }
    wmax = d[0];
#pragma unroll
    for (int i = 1; i < KNN; i++) wmax = fmaxf(wmax, d[i]);
}

// ---------------- kernel 1: pack xyz + squared norm ----------------
__global__ void pack_kernel(const float* __restrict__ xyz) {
    int i = blockIdx.x * blockDim.x + threadIdx.x;
    if (i < NQ) {
        float x = xyz[3 * i + 0];
        float y = xyz[3 * i + 1];
        float z = xyz[3 * i + 2];
        float sq = fmaf(z, z, fmaf(y, y, __fmul_rn(x, x)));
        g_pack[i] = make_float4(x, y, z, sq);
    }
}

// ---------------- kernel 2: P0 ----------------
__global__ void __launch_bounds__(256) p0_kernel(const float* __restrict__ points,
                                                 const float* __restrict__ w0,
                                                 const float* __restrict__ g0,
                                                 const float* __restrict__ rv0) {
    __shared__ float w0f[64][64];
    int tid = threadIdx.x;
    for (int e = tid; e < 4096; e += 256) {
        int o = e & 63, c = e >> 6;
        float s = fold_scale(g0[o], rv0[o]);
        w0f[c][o] = w0[o * 67 + 3 + c] * s;
    }
    __syncthreads();

    int o     = tid & 63;
    int jl    = tid >> 6;
    int jbase = blockIdx.x * 64;
#pragma unroll 1
    for (int t = 0; t < 16; t++) {
        int j = jbase + jl + (t << 2);
        const float4* prow = (const float4*)(points + (size_t)j * 64);
        float acc = 0.0f;
#pragma unroll
        for (int c4 = 0; c4 < 16; c4++) {
            float4 p = prow[c4];
            acc = fmaf(p.x, w0f[c4 * 4 + 0][o], acc);
            acc = fmaf(p.y, w0f[c4 * 4 + 1][o], acc);
            acc = fmaf(p.z, w0f[c4 * 4 + 2][o], acc);
            acc = fmaf(p.w, w0f[c4 * 4 + 3][o], acc);
        }
        g_P0[(size_t)j * 64 + o] = acc;
    }
}

// ---------------- kernel 3a: tauA ----------------
__global__ void __launch_bounds__(128) tauA_kernel() {
    int q = blockIdx.x * 128 + threadIdx.x;
    int s = blockIdx.y;
    int base  = (q >> 12) << 12;
    int cbase = base + s * TAU_SLICE_N;
    const float4* __restrict__ cand = g_pack + cbase;

    float4 me = g_pack[q];
    float qx = me.x, qy = me.y, qz = me.z, qsq = me.w;

    float d[KNN];
#pragma unroll
    for (int i = 0; i < KNN; i++) d[i] = CUDART_INF_F;
    float wmax = CUDART_INF_F;

    for (int c = 0; c < TAU_SLICE_N; c += 4) {
        float dd0 = dist2f(qx, qy, qz, qsq, cand[c + 0]);
        float dd1 = dist2f(qx, qy, qz, qsq, cand[c + 1]);
        float dd2 = dist2f(qx, qy, qz, qsq, cand[c + 2]);
        float dd3 = dist2f(qx, qy, qz, qsq, cand[c + 3]);
        if (dd0 < wmax) ins_v(dd0, d, wmax);
        if (dd1 < wmax) ins_v(dd1, d, wmax);
        if (dd2 < wmax) ins_v(dd2, d, wmax);
        if (dd3 < wmax) ins_v(dd3, d, wmax);
    }

#pragma unroll
    for (int i = 0; i < KNN; i++) g_sd[(size_t)q * 128 + s * KNN + i] = d[i];
}

// ---------------- kernel 3b: tauB ----------------
__global__ void __launch_bounds__(128) tauB_kernel() {
    int lane = threadIdx.x & 31;
    int q = blockIdx.x * 4 + (threadIdx.x >> 5);

    float4 v4 = *(const float4*)(g_sd + (size_t)q * 128 + lane * 4);
    float v0 = v4.x, v1 = v4.y, v2 = v4.z, v3 = v4.w;

    float tau = CUDART_INF_F;
#pragma unroll
    for (int it = 0; it < KNN; it++) {
        float m = fminf(fminf(v0, v1), fminf(v2, v3));
#pragma unroll
        for (int off = 16; off; off >>= 1)
            m = fminf(m, __shfl_xor_sync(0xFFFFFFFFu, m, off));
        if (v0 == m) v0 = CUDART_INF_F;
        if (v1 == m) v1 = CUDART_INF_F;
        if (v2 == m) v2 = CUDART_INF_F;
        if (v3 == m) v3 = CUDART_INF_F;
        tau = m;
    }
    if (lane == 0) g_tau[q] = tau;
}

// ---------------- kernel 3c: collect ----------------
__global__ void __launch_bounds__(128) collect_kernel() {
    int q = blockIdx.x * 128 + threadIdx.x;
    int s = blockIdx.y;
    int base  = (q >> 12) << 12;
    int cbase = base + s * COL_SLICE_N;
    const float4* __restrict__ cand = g_pack + cbase;

    float4 me = g_pack[q];
    float qx = me.x, qy = me.y, qz = me.z, qsq = me.w;
    float tau = g_tau[q];

    size_t obase = ((size_t)q * COL_SLICES + s) * COL_CAP;
    int cnt = 0;

    for (int c = 0; c < COL_SLICE_N; c += 4) {
        float dd0 = dist2f(qx, qy, qz, qsq, cand[c + 0]);
        float dd1 = dist2f(qx, qy, qz, qsq, cand[c + 1]);
        float dd2 = dist2f(qx, qy, qz, qsq, cand[c + 2]);
        float dd3 = dist2f(qx, qy, qz, qsq, cand[c + 3]);
        if (dd0 <= tau && cnt < COL_CAP) { g_cd[obase + cnt] = dd0; g_ci[obase + cnt] = cbase + c + 0; cnt++; }
        if (dd1 <= tau && cnt < COL_CAP) { g_cd[obase + cnt] = dd1; g_ci[obase + cnt] = cbase + c + 1; cnt++; }
        if (dd2 <= tau && cnt < COL_CAP) { g_cd[obase + cnt] = dd2; g_ci[obase + cnt] = cbase + c + 2; cnt++; }
        if (dd3 <= tau && cnt < COL_CAP) { g_cd[obase + cnt] = dd3; g_ci[obase + cnt] = cbase + c + 3; cnt++; }
    }
    g_cnt[q * COL_SLICES + s] = cnt;
}

// ---------------- kernel 3d: select ----------------
__global__ void __launch_bounds__(128) select_kernel() {
    int lane = threadIdx.x & 31;
    int q = blockIdx.x * 4 + (threadIdx.x >> 5);

    int cnt = (lane < COL_SLICES) ? g_cnt[q * COL_SLICES + lane] : 0;
    int pre = cnt;
#pragma unroll
    for (int off = 1; off < 8; off <<= 1) {
        int n = __shfl_up_sync(0xFFFFFFFFu, pre, off);
        if (lane >= off) pre += n;
    }
    int p0 = __shfl_sync(0xFFFFFFFFu, pre, 0);
    int p1 = __shfl_sync(0xFFFFFFFFu, pre, 1);
    int p2 = __shfl_sync(0xFFFFFFFFu, pre, 2);
    int p3 = __shfl_sync(0xFFFFFFFFu, pre, 3);
    int p4 = __shfl_sync(0xFFFFFFFFu, pre, 4);
    int p5 = __shfl_sync(0xFFFFFFFFu, pre, 5);
    int p6 = __shfl_sync(0xFFFFFFFFu, pre, 6);
    int total = __shfl_sync(0xFFFFFFFFu, pre, 7);

    unsigned long long key[16];
#pragma unroll
    for (int g = 0; g < 16; g++) {
        key[g] = ~0ull;
        int e = lane + (g << 5);
        if (e < total) {
            int s = (e >= p0) + (e >= p1) + (e >= p2) + (e >= p3)
                  + (e >= p4) + (e >= p5) + (e >= p6);
            int start = 0;
            if (s > 0) start = p0;
            if (s > 1) start = p1;
            if (s > 2) start = p2;
            if (s > 3) start = p3;
            if (s > 4) start = p4;
            if (s > 5) start = p5;
            if (s > 6) start = p6;
            size_t off = ((size_t)q * COL_SLICES + s) * COL_CAP + (e - start);
            float d  = g_cd[off];
            int   ci = g_ci[off];
            unsigned u = __float_as_uint(d);
            u = ((int)u < 0) ? ~u : (u | 0x80000000u);
            key[g] = ((unsigned long long)u << 32) | (unsigned)ci;
        }
    }

#pragma unroll 1
    for (int it = 0; it < KNN; it++) {
        unsigned long long m = key[0];
#pragma unroll
        for (int i = 1; i < 16; i++) m = (key[i] < m) ? key[i] : m;
#pragma unroll
        for (int off = 16; off; off >>= 1) {
            unsigned long long o = __shfl_xor_sync(0xFFFFFFFFu, m, off);
            m = (o < m) ? o : m;
        }
#pragma unroll
        for (int i = 0; i < 16; i++)
            if (key[i] == m) key[i] = ~0ull;
        if (lane == 0) g_idx[q * KNN + it] = (int)(m & 0xFFFFFFFFu);
    }
}

// ---------------- kernel 4: fused MLP (layers 0,1,2) + maxpool ----------------
// 128 threads = 8 queries x 16 neighbors. Dynamic smem layout (floats):
//   [0)      W1S  4096    (o*64+c, folded)
//   [4096)   W2S  8192    (o*64+c, folded)
//   [12288)  W0B  256     (64 x float4 {wx,wy,wz,b0'})
//   [12544)  B1F  64
//   [12608)  B2F  128
//   [12736)  S1   64
//   [12800)  S2   128
//   [12928)  H1T  128*65  (thread-private rows, pitch 65 -> bank (t+c)%32, no conflicts)
#define H1T_PITCH 65
#define MLP_SMEM_FLOATS (12928 + 128 * H1T_PITCH)
#define MLP_SMEM_BYTES  (MLP_SMEM_FLOATS * 4)

__global__ void __launch_bounds__(128) mlp_fused_kernel(
    const float* __restrict__ w0, const float* __restrict__ b0,
    const float* __restrict__ g0, const float* __restrict__ be0,
    const float* __restrict__ rm0, const float* __restrict__ rv0,
    const float* __restrict__ w1, const float* __restrict__ b1,
    const float* __restrict__ g1, const float* __restrict__ be1,
    const float* __restrict__ rm1, const float* __restrict__ rv1,
    const float* __restrict__ w2, const float* __restrict__ b2,
    const float* __restrict__ g2, const float* __restrict__ be2,
    const float* __restrict__ rm2, const float* __restrict__ rv2,
    float* __restrict__ out)
{
    extern __shared__ float sm[];
    float*  W1S = sm;
    float*  W2S = sm + 4096;
    float4* W0B = (float4*)(sm + 12288);
    float*  B1F = sm + 12544;
    float*  B2F = sm + 12608;
    float*  S1  = sm + 12736;
    float*  S2  = sm + 12800;
    float*  H1T = sm + 12928;

    int tid = threadIdx.x;

    // ---- fold BN into scales/biases ----
    if (tid < 64) {
        float s0 = fold_scale(g0[tid], rv0[tid]);
        W0B[tid] = make_float4(w0[tid * 67 + 0] * s0,
                               w0[tid * 67 + 1] * s0,
                               w0[tid * 67 + 2] * s0,
                               (b0[tid] - rm0[tid]) * s0 + be0[tid]);
        float s1v = fold_scale(g1[tid], rv1[tid]);
        S1[tid]  = s1v;
        B1F[tid] = (b1[tid] - rm1[tid]) * s1v + be1[tid];
    }
    {
        float s2v = fold_scale(g2[tid], rv2[tid]);
        S2[tid]  = s2v;
        B2F[tid] = (b2[tid] - rm2[tid]) * s2v + be2[tid];
    }
    __syncthreads();
    for (int e = tid; e < 4096; e += 128) W1S[e] = w1[e] * S1[e >> 6];
    for (int e = tid; e < 8192; e += 128) W2S[e] = w2[e] * S2[e >> 6];
    __syncthreads();

    int row = blockIdx.x * 128 + tid;
    int q   = row >> 4;
    int j   = g_idx[row];

    float4 pj = g_pack[j];
    float4 pq = g_pack[q];
    float rx = pj.x - pq.x, ry = pj.y - pq.y, rz = pj.z - pq.z;

    // ---- layer 0: h0 = relu(P0[j] + W0x . rel + b0') ----
    float h0[64];
    const float4* p0row = (const float4*)(g_P0 + (size_t)j * 64);
#pragma unroll
    for (int o4 = 0; o4 < 16; o4++) {
        float4 p = p0row[o4];
        float pv[4] = { p.x, p.y, p.z, p.w };
#pragma unroll
        for (int u = 0; u < 4; u++) {
            int o = o4 * 4 + u;
            float4 w = W0B[o];
            float v = fmaf(w.x, rx, fmaf(w.y, ry, fmaf(w.z, rz, pv[u] + w.w)));
            h0[o] = fmaxf(v, 0.0f);
        }
    }

    // ---- layer 1: stream h1 into thread-private smem row (no sync needed) ----
    float* hrow = H1T + tid * H1T_PITCH;
#pragma unroll 1
    for (int o4 = 0; o4 < 16; o4++) {
        float a0 = B1F[o4 * 4 + 0], a1 = B1F[o4 * 4 + 1];
        float a2 = B1F[o4 * 4 + 2], a3 = B1F[o4 * 4 + 3];
        const float4* wr0 = (const float4*)(W1S + (o4 * 4 + 0) * 64);
        const float4* wr1 = (const float4*)(W1S + (o4 * 4 + 1) * 64);
        const float4* wr2 = (const float4*)(W1S + (o4 * 4 + 2) * 64);
        const float4* wr3 = (const float4*)(W1S + (o4 * 4 + 3) * 64);
#pragma unroll
        for (int c4 = 0; c4 < 16; c4++) {
            float4 x0 = wr0[c4], x1 = wr1[c4], x2 = wr2[c4], x3 = wr3[c4];
            float hA = h0[c4 * 4 + 0], hB = h0[c4 * 4 + 1];
            float hC = h0[c4 * 4 + 2], hD = h0[c4 * 4 + 3];
            a0 = fmaf(x0.x, hA, a0); a0 = fmaf(x0.y, hB, a0);
            a0 = fmaf(x0.z, hC, a0); a0 = fmaf(x0.w, hD, a0);
            a1 = fmaf(x1.x, hA, a1); a1 = fmaf(x1.y, hB, a1);
            a1 = fmaf(x1.z, hC, a1); a1 = fmaf(x1.w, hD, a1);
            a2 = fmaf(x2.x, hA, a2); a2 = fmaf(x2.y, hB, a2);
            a2 = fmaf(x2.z, hC, a2); a2 = fmaf(x2.w, hD, a2);
            a3 = fmaf(x3.x, hA, a3); a3 = fmaf(x3.y, hB, a3);
            a3 = fmaf(x3.z, hC, a3); a3 = fmaf(x3.w, hD, a3);
        }
        hrow[o4 * 4 + 0] = fmaxf(a0, 0.0f);
        hrow[o4 * 4 + 1] = fmaxf(a1, 0.0f);
        hrow[o4 * 4 + 2] = fmaxf(a2, 0.0f);
        hrow[o4 * 4 + 3] = fmaxf(a3, 0.0f);
    }

    // ---- read h1 back (registers vacated by h0) ----
    float h1[64];
#pragma unroll
    for (int c = 0; c < 64; c++) h1[c] = hrow[c];

    // ---- layer 2 + maxpool over 16 neighbors ----
    int lane = tid & 31;
    float* orow = out + (size_t)q * C2;
#pragma unroll 2
    for (int o = 0; o < C2; o++) {
        const float4* wr = (const float4*)(W2S + o * 64);
        float acc = B2F[o];
#pragma unroll
        for (int c4 = 0; c4 < 16; c4++) {
            float4 a = wr[c4];
            acc = fmaf(a.x, h1[c4 * 4 + 0], acc);
            acc = fmaf(a.y, h1[c4 * 4 + 1], acc);
            acc = fmaf(a.z, h1[c4 * 4 + 2], acc);
            acc = fmaf(a.w, h1[c4 * 4 + 3], acc);
        }
        float v = fmaxf(acc, 0.0f);
        v = fmaxf(v, __shfl_xor_sync(0xFFFFFFFFu, v, 1));
        v = fmaxf(v, __shfl_xor_sync(0xFFFFFFFFu, v, 2));
        v = fmaxf(v, __shfl_xor_sync(0xFFFFFFFFu, v, 4));
        v = fmaxf(v, __shfl_xor_sync(0xFFFFFFFFu, v, 8));
        if ((lane & 15) == 0) orow[o] = v;
    }
}

// ---------------- launch ----------------
extern "C" void kernel_launch(void* const* d_in, const int* in_sizes, int n_in,
                              void* d_out, int out_size) {
    (void)in_sizes; (void)n_in; (void)out_size;
    const float* xyz    = (const float*)d_in[0];
    const float* points = (const float*)d_in[1];
    const float* w0  = (const float*)d_in[2];
    const float* b0  = (const float*)d_in[3];
    const float* g0  = (const float*)d_in[4];
    const float* be0 = (const float*)d_in[5];
    const float* rm0 = (const float*)d_in[6];
    const float* rv0 = (const float*)d_in[7];
    const float* w1  = (const float*)d_in[8];
    const float* b1  = (const float*)d_in[9];
    const float* g1  = (const float*)d_in[10];
    const float* be1 = (const float*)d_in[11];
    const float* rm1 = (const float*)d_in[12];
    const float* rv1 = (const float*)d_in[13];
    const float* w2  = (const float*)d_in[14];
    const float* b2  = (const float*)d_in[15];
    const float* g2  = (const float*)d_in[16];
    const float* be2 = (const float*)d_in[17];
    const float* rm2 = (const float*)d_in[18];
    const float* rv2 = (const float*)d_in[19];
    float* out = (float*)d_out;

    cudaFuncSetAttribute(mlp_fused_kernel,
                         cudaFuncAttributeMaxDynamicSharedMemorySize, MLP_SMEM_BYTES);

    pack_kernel<<<NQ / 256, 256>>>(xyz);
    p0_kernel<<<NQ / 64, 256>>>(points, w0, g0, rv0);
    tauA_kernel<<<dim3(NQ / 128, TAU_SLICES), 128>>>();
    tauB_kernel<<<NQ / 4, 128>>>();
    collect_kernel<<<dim3(NQ / 128, COL_SLICES), 128>>>();
    select_kernel<<<NQ / 4, 128>>>();
    mlp_fused_kernel<<<NROWS / 128, 128, MLP_SMEM_BYTES>>>(
        w0, b0, g0, be0, rm0, rv0,
        w1, b1, g1, be1, rm1, rv1,
        w2, b2, g2, be2, rm2, rv2, out);
}

// round 13
// speedup vs baseline: 1.9054x; 1.6293x over previous
#include <cuda_runtime.h>
#include <cuda_bf16.h>
#include <math_constants.h>
#include <cstdint>

#define BATCH  4
#define NPTS   4096
#define NQ     (BATCH * NPTS)   // 16384
#define KNN    16
#define NROWS  (NQ * KNN)       // 262144
#define C2     128
#define EPSBN  1e-5f

#define TAU_SLICES   8
#define TAU_SLICE_N  64
#define COL_SLICES   8
#define COL_SLICE_N  512
#define COL_CAP      64

// ---------------- scratch (no device allocations allowed) ----------------
__device__ float4 g_pack[NQ];
__device__ int    g_idx[NROWS];
__device__ float  g_P0[NQ * 64];
__device__ float  g_sd[NQ * 128];
__device__ float  g_tau[NQ];
__device__ float  g_cd[(size_t)NQ * COL_SLICES * COL_CAP];
__device__ int    g_ci[(size_t)NQ * COL_SLICES * COL_CAP];
__device__ int    g_cnt[NQ * COL_SLICES];
// folded weights: W1H(2304w) W1L(2304w) W2H(4608w) W2L(4608w) B1(64w) B2(128w)
// rows padded to pitch 36 words (72 bf16) for conflict-free fragment loads
__device__ __align__(16) uint32_t g_fold[14016];
__device__ float4 g_W0Bd[64];

// ---------------- helpers ----------------
__device__ __forceinline__ float fold_scale(float g, float rv) {
    float v = rv + EPSBN;
    float r = rsqrtf(v);
    r = r * (1.5f - 0.5f * v * r * r);
    return g * r;
}

__device__ __forceinline__ float dist2f(float qx, float qy, float qz, float qsq, float4 p) {
    float dot = fmaf(qz, p.z, fmaf(qy, p.y, __fmul_rn(qx, p.x)));
    return __fadd_rn(__fadd_rn(qsq, p.w), __fmul_rn(-2.0f, dot));
}

__device__ __forceinline__ void ins_v(float dd, float* d, float& wmax) {
    bool done = false;
#pragma unroll
    for (int i = 0; i < KNN; i++) {
        bool m = (!done) && (d[i] == wmax);
        if (m) d[i] = dd;
        done = done || m;
    }
    wmax = d[0];
#pragma unroll
    for (int i = 1; i < KNN; i++) wmax = fmaxf(wmax, d[i]);
}

// hi/lo bf16 split of two floats: hiw = {bf16(v0) lo-half, bf16(v1) hi-half}
__device__ __forceinline__ void split2(float v0, float v1, uint32_t& hiw, uint32_t& low) {
    __nv_bfloat16 h0 = __float2bfloat16(v0);
    __nv_bfloat16 h1 = __float2bfloat16(v1);
    __nv_bfloat16 l0 = __float2bfloat16(v0 - __bfloat162float(h0));
    __nv_bfloat16 l1 = __float2bfloat16(v1 - __bfloat162float(h1));
    __nv_bfloat162 hp; hp.x = h0; hp.y = h1;
    __nv_bfloat162 lp; lp.x = l0; lp.y = l1;
    hiw = *(uint32_t*)&hp;
    low = *(uint32_t*)&lp;
}

// warp-level bf16 MMA, fp32 accum (Ampere+ mma.sync — no TMEM/mbarrier surface)
__device__ __forceinline__ void mma16816(float* d, const uint32_t* a,
                                         uint32_t b0, uint32_t b1) {
    asm volatile(
        "mma.sync.aligned.m16n8k16.row.col.f32.bf16.bf16.f32 "
        "{%0,%1,%2,%3}, {%4,%5,%6,%7}, {%8,%9}, {%0,%1,%2,%3};"
        : "+f"(d[0]), "+f"(d[1]), "+f"(d[2]), "+f"(d[3])
        : "r"(a[0]), "r"(a[1]), "r"(a[2]), "r"(a[3]), "r"(b0), "r"(b1));
}

// ---------------- kernel 1: pack xyz + squared norm ----------------
__global__ void pack_kernel(const float* __restrict__ xyz) {
    int i = blockIdx.x * blockDim.x + threadIdx.x;
    if (i < NQ) {
        float x = xyz[3 * i + 0];
        float y = xyz[3 * i + 1];
        float z = xyz[3 * i + 2];
        float sq = fmaf(z, z, fmaf(y, y, __fmul_rn(x, x)));
        g_pack[i] = make_float4(x, y, z, sq);
    }
}

// ---------------- kernel 2: P0 ----------------
__global__ void __launch_bounds__(256) p0_kernel(const float* __restrict__ points,
                                                 const float* __restrict__ w0,
                                                 const float* __restrict__ g0,
                                                 const float* __restrict__ rv0) {
    __shared__ float w0f[64][64];
    int tid = threadIdx.x;
    for (int e = tid; e < 4096; e += 256) {
        int o = e & 63, c = e >> 6;
        float s = fold_scale(g0[o], rv0[o]);
        w0f[c][o] = w0[o * 67 + 3 + c] * s;
    }
    __syncthreads();

    int o     = tid & 63;
    int jl    = tid >> 6;
    int jbase = blockIdx.x * 64;
#pragma unroll 1
    for (int t = 0; t < 16; t++) {
        int j = jbase + jl + (t << 2);
        const float4* prow = (const float4*)(points + (size_t)j * 64);
        float acc = 0.0f;
#pragma unroll
        for (int c4 = 0; c4 < 16; c4++) {
            float4 p = prow[c4];
            acc = fmaf(p.x, w0f[c4 * 4 + 0][o], acc);
            acc = fmaf(p.y, w0f[c4 * 4 + 1][o], acc);
            acc = fmaf(p.z, w0f[c4 * 4 + 2][o], acc);
            acc = fmaf(p.w, w0f[c4 * 4 + 3][o], acc);
        }
        g_P0[(size_t)j * 64 + o] = acc;
    }
}

// ---------------- kernel 3a: tauA ----------------
__global__ void __launch_bounds__(128) tauA_kernel() {
    int q = blockIdx.x * 128 + threadIdx.x;
    int s = blockIdx.y;
    int base  = (q >> 12) << 12;
    int cbase = base + s * TAU_SLICE_N;
    const float4* __restrict__ cand = g_pack + cbase;

    float4 me = g_pack[q];
    float qx = me.x, qy = me.y, qz = me.z, qsq = me.w;

    float d[KNN];
#pragma unroll
    for (int i = 0; i < KNN; i++) d[i] = CUDART_INF_F;
    float wmax = CUDART_INF_F;

    for (int c = 0; c < TAU_SLICE_N; c += 4) {
        float dd0 = dist2f(qx, qy, qz, qsq, cand[c + 0]);
        float dd1 = dist2f(qx, qy, qz, qsq, cand[c + 1]);
        float dd2 = dist2f(qx, qy, qz, qsq, cand[c + 2]);
        float dd3 = dist2f(qx, qy, qz, qsq, cand[c + 3]);
        if (dd0 < wmax) ins_v(dd0, d, wmax);
        if (dd1 < wmax) ins_v(dd1, d, wmax);
        if (dd2 < wmax) ins_v(dd2, d, wmax);
        if (dd3 < wmax) ins_v(dd3, d, wmax);
    }

#pragma unroll
    for (int i = 0; i < KNN; i++) g_sd[(size_t)q * 128 + s * KNN + i] = d[i];
}

// ---------------- kernel 3b: tauB ----------------
__global__ void __launch_bounds__(128) tauB_kernel() {
    int lane = threadIdx.x & 31;
    int q = blockIdx.x * 4 + (threadIdx.x >> 5);

    float4 v4 = *(const float4*)(g_sd + (size_t)q * 128 + lane * 4);
    float v0 = v4.x, v1 = v4.y, v2 = v4.z, v3 = v4.w;

    float tau = CUDART_INF_F;
#pragma unroll
    for (int it = 0; it < KNN; it++) {
        float m = fminf(fminf(v0, v1), fminf(v2, v3));
#pragma unroll
        for (int off = 16; off; off >>= 1)
            m = fminf(m, __shfl_xor_sync(0xFFFFFFFFu, m, off));
        if (v0 == m) v0 = CUDART_INF_F;
        if (v1 == m) v1 = CUDART_INF_F;
        if (v2 == m) v2 = CUDART_INF_F;
        if (v3 == m) v3 = CUDART_INF_F;
        tau = m;
    }
    if (lane == 0) g_tau[q] = tau;
}

// ---------------- kernel 3c: collect ----------------
__global__ void __launch_bounds__(128) collect_kernel() {
    int q = blockIdx.x * 128 + threadIdx.x;
    int s = blockIdx.y;
    int base  = (q >> 12) << 12;
    int cbase = base + s * COL_SLICE_N;
    const float4* __restrict__ cand = g_pack + cbase;

    float4 me = g_pack[q];
    float qx = me.x, qy = me.y, qz = me.z, qsq = me.w;
    float tau = g_tau[q];

    size_t obase = ((size_t)q * COL_SLICES + s) * COL_CAP;
    int cnt = 0;

    for (int c = 0; c < COL_SLICE_N; c += 4) {
        float dd0 = dist2f(qx, qy, qz, qsq, cand[c + 0]);
        float dd1 = dist2f(qx, qy, qz, qsq, cand[c + 1]);
        float dd2 = dist2f(qx, qy, qz, qsq, cand[c + 2]);
        float dd3 = dist2f(qx, qy, qz, qsq, cand[c + 3]);
        if (dd0 <= tau && cnt < COL_CAP) { g_cd[obase + cnt] = dd0; g_ci[obase + cnt] = cbase + c + 0; cnt++; }
        if (dd1 <= tau && cnt < COL_CAP) { g_cd[obase + cnt] = dd1; g_ci[obase + cnt] = cbase + c + 1; cnt++; }
        if (dd2 <= tau && cnt < COL_CAP) { g_cd[obase + cnt] = dd2; g_ci[obase + cnt] = cbase + c + 2; cnt++; }
        if (dd3 <= tau && cnt < COL_CAP) { g_cd[obase + cnt] = dd3; g_ci[obase + cnt] = cbase + c + 3; cnt++; }
    }
    g_cnt[q * COL_SLICES + s] = cnt;
}

// ---------------- kernel 3d: select ----------------
__global__ void __launch_bounds__(128) select_kernel() {
    int lane = threadIdx.x & 31;
    int q = blockIdx.x * 4 + (threadIdx.x >> 5);

    int cnt = (lane < COL_SLICES) ? g_cnt[q * COL_SLICES + lane] : 0;
    int pre = cnt;
#pragma unroll
    for (int off = 1; off < 8; off <<= 1) {
        int n = __shfl_up_sync(0xFFFFFFFFu, pre, off);
        if (lane >= off) pre += n;
    }
    int p0 = __shfl_sync(0xFFFFFFFFu, pre, 0);
    int p1 = __shfl_sync(0xFFFFFFFFu, pre, 1);
    int p2 = __shfl_sync(0xFFFFFFFFu, pre, 2);
    int p3 = __shfl_sync(0xFFFFFFFFu, pre, 3);
    int p4 = __shfl_sync(0xFFFFFFFFu, pre, 4);
    int p5 = __shfl_sync(0xFFFFFFFFu, pre, 5);
    int p6 = __shfl_sync(0xFFFFFFFFu, pre, 6);
    int total = __shfl_sync(0xFFFFFFFFu, pre, 7);

    unsigned long long key[16];
#pragma unroll
    for (int g = 0; g < 16; g++) {
        key[g] = ~0ull;
        int e = lane + (g << 5);
        if (e < total) {
            int s = (e >= p0) + (e >= p1) + (e >= p2) + (e >= p3)
                  + (e >= p4) + (e >= p5) + (e >= p6);
            int start = 0;
            if (s > 0) start = p0;
            if (s > 1) start = p1;
            if (s > 2) start = p2;
            if (s > 3) start = p3;
            if (s > 4) start = p4;
            if (s > 5) start = p5;
            if (s > 6) start = p6;
            size_t off = ((size_t)q * COL_SLICES + s) * COL_CAP + (e - start);
            float d  = g_cd[off];
            int   ci = g_ci[off];
            unsigned u = __float_as_uint(d);
            u = ((int)u < 0) ? ~u : (u | 0x80000000u);
            key[g] = ((unsigned long long)u << 32) | (unsigned)ci;
        }
    }

#pragma unroll 1
    for (int it = 0; it < KNN; it++) {
        unsigned long long m = key[0];
#pragma unroll
        for (int i = 1; i < 16; i++) m = (key[i] < m) ? key[i] : m;
#pragma unroll
        for (int off = 16; off; off >>= 1) {
            unsigned long long o = __shfl_xor_sync(0xFFFFFFFFu, m, off);
            m = (o < m) ? o : m;
        }
#pragma unroll
        for (int i = 0; i < 16; i++)
            if (key[i] == m) key[i] = ~0ull;
        if (lane == 0) g_idx[q * KNN + it] = (int)(m & 0xFFFFFFFFu);
    }
}

// ---------------- kernel 3.5: fold weights -> packed bf16 hi/lo, pitch 36 words --
__global__ void __launch_bounds__(128) foldw_kernel(
    const float* __restrict__ w0, const float* __restrict__ b0,
    const float* __restrict__ g0, const float* __restrict__ be0,
    const float* __restrict__ rm0, const float* __restrict__ rv0,
    const float* __restrict__ w1, const float* __restrict__ b1,
    const float* __restrict__ g1, const float* __restrict__ be1,
    const float* __restrict__ rm1, const float* __restrict__ rv1,
    const float* __restrict__ w2, const float* __restrict__ b2,
    const float* __restrict__ g2, const float* __restrict__ be2,
    const float* __restrict__ rm2, const float* __restrict__ rv2)
{
    int tid = threadIdx.x;
    if (tid < 64) {
        float s0 = fold_scale(g0[tid], rv0[tid]);
        g_W0Bd[tid] = make_float4(w0[tid * 67 + 0] * s0,
                                  w0[tid * 67 + 1] * s0,
                                  w0[tid * 67 + 2] * s0,
                                  (b0[tid] - rm0[tid]) * s0 + be0[tid]);
        float s1 = fold_scale(g1[tid], rv1[tid]);
        g_fold[13824 + tid] = __float_as_uint((b1[tid] - rm1[tid]) * s1 + be1[tid]);
    }
    {
        float s2 = fold_scale(g2[tid], rv2[tid]);
        g_fold[13888 + tid] = __float_as_uint((b2[tid] - rm2[tid]) * s2 + be2[tid]);
    }
    // W1 [64][64] -> W1H @0, W1L @2304 (pitch 36 words)
    for (int e = tid; e < 2048; e += 128) {
        int o = e >> 5, c2 = e & 31, c = 2 * c2;
        float s = fold_scale(g1[o], rv1[o]);
        uint32_t hw, lw;
        split2(w1[o * 64 + c] * s, w1[o * 64 + c + 1] * s, hw, lw);
        g_fold[o * 36 + c2]        = hw;
        g_fold[2304 + o * 36 + c2] = lw;
    }
    // W2 [128][64] -> W2H @4608, W2L @9216
    for (int e = tid; e < 4096; e += 128) {
        int o = e >> 5, c2 = e & 31, c = 2 * c2;
        float s = fold_scale(g2[o], rv2[o]);
        uint32_t hw, lw;
        split2(w2[o * 64 + c] * s, w2[o * 64 + c + 1] * s, hw, lw);
        g_fold[4608 + o * 36 + c2] = hw;
        g_fold[9216 + o * 36 + c2] = lw;
    }
}

// ---------------- kernel 4: fused MLP via mma.sync (bf16 3-term split) ----------
// smem (uint32 words): HHI[128*36] @0, HLO @4608, then g_fold image @9216 (14016w)
#define SW_HHI 0
#define SW_HLO 4608
#define SW_W   9216
#define SW_W1H (SW_W + 0)
#define SW_W1L (SW_W + 2304)
#define SW_W2H (SW_W + 4608)
#define SW_W2L (SW_W + 9216)
#define SW_B1  (SW_W + 13824)
#define SW_B2  (SW_W + 13888)
#define SW_WORDS (SW_W + 14016)          // 23232 words = 92928 bytes
#define MLPMMA_SMEM (SW_WORDS * 4)

__global__ void __launch_bounds__(128) mlp_mma_kernel(float* __restrict__ out) {
    extern __shared__ __align__(16) uint32_t smw[];
    float* smf = (float*)smw;
    int tid = threadIdx.x;

    // copy folded weights + biases (14016 words = 3504 uint4)
    {
        uint4* dst = (uint4*)(smw + SW_W);
        const uint4* src = (const uint4*)g_fold;
        for (int e = tid; e < 3504; e += 128) dst[e] = src[e];
    }

    // ---- layer 0 (scalar) -> H0 hi/lo in smem ----
    int row = blockIdx.x * 128 + tid;
    int q   = row >> 4;
    int j   = g_idx[row];

    float4 pj = g_pack[j];
    float4 pq = g_pack[q];
    float rx = pj.x - pq.x, ry = pj.y - pq.y, rz = pj.z - pq.z;

    const float4* p0row = (const float4*)(g_P0 + (size_t)j * 64);
#pragma unroll
    for (int o4 = 0; o4 < 16; o4++) {
        float4 p = p0row[o4];
        float pv[4] = { p.x, p.y, p.z, p.w };
        float hv[4];
#pragma unroll
        for (int u = 0; u < 4; u++) {
            float4 w = g_W0Bd[o4 * 4 + u];
            float v = fmaf(w.x, rx, fmaf(w.y, ry, fmaf(w.z, rz, pv[u] + w.w)));
            hv[u] = fmaxf(v, 0.0f);
        }
        uint32_t hw, lw;
        split2(hv[0], hv[1], hw, lw);
        smw[SW_HHI + tid * 36 + o4 * 2]     = hw;
        smw[SW_HLO + tid * 36 + o4 * 2]     = lw;
        split2(hv[2], hv[3], hw, lw);
        smw[SW_HHI + tid * 36 + o4 * 2 + 1] = hw;
        smw[SW_HLO + tid * 36 + o4 * 2 + 1] = lw;
    }
    __syncthreads();

    int w    = tid >> 5;
    int lane = tid & 31;
    int g    = lane >> 2;
    int t    = lane & 3;
    int m0   = w * 32;

    // A fragments: [mt][kt][4]; a0=(g,klo) a1=(g+8,klo) a2=(g,khi) a3=(g+8,khi)
    uint32_t Ah[2][4][4], Al[2][4][4];
#pragma unroll
    for (int mt = 0; mt < 2; mt++) {
        int r0 = (m0 + mt * 16 + g) * 36;
        int r1 = r0 + 8 * 36;
#pragma unroll
        for (int kt = 0; kt < 4; kt++) {
            int cw = kt * 8 + t;
            Ah[mt][kt][0] = smw[SW_HHI + r0 + cw];
            Ah[mt][kt][1] = smw[SW_HHI + r1 + cw];
            Ah[mt][kt][2] = smw[SW_HHI + r0 + cw + 4];
            Ah[mt][kt][3] = smw[SW_HHI + r1 + cw + 4];
            Al[mt][kt][0] = smw[SW_HLO + r0 + cw];
            Al[mt][kt][1] = smw[SW_HLO + r1 + cw];
            Al[mt][kt][2] = smw[SW_HLO + r0 + cw + 4];
            Al[mt][kt][3] = smw[SW_HLO + r1 + cw + 4];
        }
    }

    // ---- layer 1: 8 n-tiles (N=64), 2 per iteration; write h1 back to H ----
#pragma unroll 1
    for (int np = 0; np < 4; np++) {
        float acc[2][2][4];
#pragma unroll
        for (int mt = 0; mt < 2; mt++)
#pragma unroll
            for (int nn = 0; nn < 2; nn++)
#pragma unroll
                for (int i = 0; i < 4; i++) acc[mt][nn][i] = 0.0f;

#pragma unroll
        for (int kt = 0; kt < 4; kt++) {
#pragma unroll
            for (int nn = 0; nn < 2; nn++) {
                int n0 = (np * 2 + nn) * 8;
                int bw = (n0 + g) * 36 + kt * 8 + t;
                uint32_t bh0 = smw[SW_W1H + bw], bh1 = smw[SW_W1H + bw + 4];
                uint32_t bl0 = smw[SW_W1L + bw], bl1 = smw[SW_W1L + bw + 4];
#pragma unroll
                for (int mt = 0; mt < 2; mt++) {
                    mma16816(acc[mt][nn], Ah[mt][kt], bh0, bh1);
                    mma16816(acc[mt][nn], Ah[mt][kt], bl0, bl1);
                    mma16816(acc[mt][nn], Al[mt][kt], bh0, bh1);
                }
            }
        }
#pragma unroll
        for (int nn = 0; nn < 2; nn++) {
            int n0 = (np * 2 + nn) * 8;
            float bias0 = smf[SW_B1 + n0 + 2 * t];
            float bias1 = smf[SW_B1 + n0 + 2 * t + 1];
#pragma unroll
            for (int mt = 0; mt < 2; mt++) {
                int r0 = (m0 + mt * 16 + g) * 36;
                int cw = n0 / 2 + t;
                float v0 = fmaxf(acc[mt][nn][0] + bias0, 0.0f);
                float v1 = fmaxf(acc[mt][nn][1] + bias1, 0.0f);
                float v2 = fmaxf(acc[mt][nn][2] + bias0, 0.0f);
                float v3 = fmaxf(acc[mt][nn][3] + bias1, 0.0f);
                uint32_t hw, lw;
                split2(v0, v1, hw, lw);
                smw[SW_HHI + r0 + cw] = hw;
                smw[SW_HLO + r0 + cw] = lw;
                split2(v2, v3, hw, lw);
                smw[SW_HHI + r0 + 288 + cw] = hw;
                smw[SW_HLO + r0 + 288 + cw] = lw;
            }
        }
    }
    __syncwarp();   // warp-private rows: warp-level visibility suffices

    // reload A fragments (now h1)
#pragma unroll
    for (int mt = 0; mt < 2; mt++) {
        int r0 = (m0 + mt * 16 + g) * 36;
        int r1 = r0 + 8 * 36;
#pragma unroll
        for (int kt = 0; kt < 4; kt++) {
            int cw = kt * 8 + t;
            Ah[mt][kt][0] = smw[SW_HHI + r0 + cw];
            Ah[mt][kt][1] = smw[SW_HHI + r1 + cw];
            Ah[mt][kt][2] = smw[SW_HHI + r0 + cw + 4];
            Ah[mt][kt][3] = smw[SW_HHI + r1 + cw + 4];
            Al[mt][kt][0] = smw[SW_HLO + r0 + cw];
            Al[mt][kt][1] = smw[SW_HLO + r1 + cw];
            Al[mt][kt][2] = smw[SW_HLO + r0 + cw + 4];
            Al[mt][kt][3] = smw[SW_HLO + r1 + cw + 4];
        }
    }

    // ---- layer 2 (N=128) + maxpool; one m16-tile == one query's 16 rows ----
#pragma unroll 1
    for (int np = 0; np < 8; np++) {
        float acc[2][2][4];
#pragma unroll
        for (int mt = 0; mt < 2; mt++)
#pragma unroll
            for (int nn = 0; nn < 2; nn++)
#pragma unroll
                for (int i = 0; i < 4; i++) acc[mt][nn][i] = 0.0f;

#pragma unroll
        for (int kt = 0; kt < 4; kt++) {
#pragma unroll
            for (int nn = 0; nn < 2; nn++) {
                int n0 = (np * 2 + nn) * 8;
                int bw = (n0 + g) * 36 + kt * 8 + t;
                uint32_t bh0 = smw[SW_W2H + bw], bh1 = smw[SW_W2H + bw + 4];
                uint32_t bl0 = smw[SW_W2L + bw], bl1 = smw[SW_W2L + bw + 4];
#pragma unroll
                for (int mt = 0; mt < 2; mt++) {
                    mma16816(acc[mt][nn], Ah[mt][kt], bh0, bh1);
                    mma16816(acc[mt][nn], Ah[mt][kt], bl0, bl1);
                    mma16816(acc[mt][nn], Al[mt][kt], bh0, bh1);
                }
            }
        }
#pragma unroll
        for (int nn = 0; nn < 2; nn++) {
            int n0 = (np * 2 + nn) * 8;
            float bias0 = smf[SW_B2 + n0 + 2 * t];
            float bias1 = smf[SW_B2 + n0 + 2 * t + 1];
#pragma unroll
            for (int mt = 0; mt < 2; mt++) {
                float m01 = fmaxf(fmaxf(acc[mt][nn][0] + bias0, 0.0f),
                                  fmaxf(acc[mt][nn][2] + bias0, 0.0f));
                float m23 = fmaxf(fmaxf(acc[mt][nn][1] + bias1, 0.0f),
                                  fmaxf(acc[mt][nn][3] + bias1, 0.0f));
#pragma unroll
                for (int off = 4; off <= 16; off <<= 1) {
                    m01 = fmaxf(m01, __shfl_xor_sync(0xFFFFFFFFu, m01, off));
                    m23 = fmaxf(m23, __shfl_xor_sync(0xFFFFFFFFu, m23, off));
                }
                if (g == 0) {
                    int qq = blockIdx.x * 8 + w * 2 + mt;
                    out[(size_t)qq * C2 + n0 + 2 * t]     = m01;
                    out[(size_t)qq * C2 + n0 + 2 * t + 1] = m23;
                }
            }
        }
    }
}

// ---------------- launch ----------------
extern "C" void kernel_launch(void* const* d_in, const int* in_sizes, int n_in,
                              void* d_out, int out_size) {
    (void)in_sizes; (void)n_in; (void)out_size;
    const float* xyz    = (const float*)d_in[0];
    const float* points = (const float*)d_in[1];
    const float* w0  = (const float*)d_in[2];
    const float* b0  = (const float*)d_in[3];
    const float* g0  = (const float*)d_in[4];
    const float* be0 = (const float*)d_in[5];
    const float* rm0 = (const float*)d_in[6];
    const float* rv0 = (const float*)d_in[7];
    const float* w1  = (const float*)d_in[8];
    const float* b1  = (const float*)d_in[9];
    const float* g1  = (const float*)d_in[10];
    const float* be1 = (const float*)d_in[11];
    const float* rm1 = (const float*)d_in[12];
    const float* rv1 = (const float*)d_in[13];
    const float* w2  = (const float*)d_in[14];
    const float* b2  = (const float*)d_in[15];
    const float* g2  = (const float*)d_in[16];
    const float* be2 = (const float*)d_in[17];
    const float* rm2 = (const float*)d_in[18];
    const float* rv2 = (const float*)d_in[19];
    float* out = (float*)d_out;

    cudaFuncSetAttribute(mlp_mma_kernel,
                         cudaFuncAttributeMaxDynamicSharedMemorySize, MLPMMA_SMEM);

    pack_kernel<<<NQ / 256, 256>>>(xyz);
    p0_kernel<<<NQ / 64, 256>>>(points, w0, g0, rv0);
    tauA_kernel<<<dim3(NQ / 128, TAU_SLICES), 128>>>();
    tauB_kernel<<<NQ / 4, 128>>>();
    collect_kernel<<<dim3(NQ / 128, COL_SLICES), 128>>>();
    select_kernel<<<NQ / 4, 128>>>();
    foldw_kernel<<<1, 128>>>(w0, b0, g0, be0, rm0, rv0,
                             w1, b1, g1, be1, rm1, rv1,
                             w2, b2, g2, be2, rm2, rv2);
    mlp_mma_kernel<<<NROWS / 128, 128, MLPMMA_SMEM>>>(out);
}

// round 15
// speedup vs baseline: 2.4048x; 1.2621x over previous
#include <cuda_runtime.h>
#include <cuda_bf16.h>
#include <math_constants.h>
#include <cstdint>

#define BATCH  4
#define NPTS   4096
#define NQ     (BATCH * NPTS)   // 16384
#define KNN    16
#define NROWS  (NQ * KNN)       // 262144
#define C2     128
#define EPSBN  1e-5f
#define CAP    384              // survivor cap per query (+8 sigma)

// ---------------- scratch (no device allocations allowed) ----------------
__device__ float4 g_pack[NQ];
__device__ int    g_idx[NROWS];
__device__ float  g_P0[NQ * 64];
__device__ float  g_tau[NQ];
// folded weights: W1H(2304w) W1L(2304w) W2H(4608w) W2L(4608w) B1(64w) B2(128w)
__device__ __align__(16) uint32_t g_fold[14016];
__device__ float4 g_W0Bd[64];

// ---------------- helpers ----------------
__device__ __forceinline__ float fold_scale(float g, float rv) {
    float v = rv + EPSBN;
    float r = rsqrtf(v);
    r = r * (1.5f - 0.5f * v * r * r);
    return g * r;
}

__device__ __forceinline__ float dist2f(float qx, float qy, float qz, float qsq, float4 p) {
    float dot = fmaf(qz, p.z, fmaf(qy, p.y, __fmul_rn(qx, p.x)));
    return __fadd_rn(__fadd_rn(qsq, p.w), __fmul_rn(-2.0f, dot));
}

// hi/lo bf16 split of two floats
__device__ __forceinline__ void split2(float v0, float v1, uint32_t& hiw, uint32_t& low) {
    __nv_bfloat16 h0 = __float2bfloat16(v0);
    __nv_bfloat16 h1 = __float2bfloat16(v1);
    __nv_bfloat16 l0 = __float2bfloat16(v0 - __bfloat162float(h0));
    __nv_bfloat16 l1 = __float2bfloat16(v1 - __bfloat162float(h1));
    __nv_bfloat162 hp; hp.x = h0; hp.y = h1;
    __nv_bfloat162 lp; lp.x = l0; lp.y = l1;
    hiw = *(uint32_t*)&hp;
    low = *(uint32_t*)&lp;
}

// warp-level bf16 MMA, fp32 accum
__device__ __forceinline__ void mma16816(float* d, const uint32_t* a,
                                         uint32_t b0, uint32_t b1) {
    asm volatile(
        "mma.sync.aligned.m16n8k16.row.col.f32.bf16.bf16.f32 "
        "{%0,%1,%2,%3}, {%4,%5,%6,%7}, {%8,%9}, {%0,%1,%2,%3};"
        : "+f"(d[0]), "+f"(d[1]), "+f"(d[2]), "+f"(d[3])
        : "r"(a[0]), "r"(a[1]), "r"(a[2]), "r"(a[3]), "r"(b0), "r"(b1));
}

// ---------------- kernel 1: prep = pack + p0 + foldw ----------------
__global__ void __launch_bounds__(256) prep_kernel(
    const float* __restrict__ xyz, const float* __restrict__ points,
    const float* __restrict__ w0, const float* __restrict__ b0,
    const float* __restrict__ g0, const float* __restrict__ be0,
    const float* __restrict__ rm0, const float* __restrict__ rv0,
    const float* __restrict__ w1, const float* __restrict__ b1,
    const float* __restrict__ g1, const float* __restrict__ be1,
    const float* __restrict__ rm1, const float* __restrict__ rv1,
    const float* __restrict__ w2, const float* __restrict__ b2,
    const float* __restrict__ g2, const float* __restrict__ be2,
    const float* __restrict__ rm2, const float* __restrict__ rv2)
{
    __shared__ float w0f[64][64];
    int tid = threadIdx.x;

    if (blockIdx.x == 256) {
        // ---- foldw ----
        if (tid < 64) {
            float s0 = fold_scale(g0[tid], rv0[tid]);
            g_W0Bd[tid] = make_float4(w0[tid * 67 + 0] * s0,
                                      w0[tid * 67 + 1] * s0,
                                      w0[tid * 67 + 2] * s0,
                                      (b0[tid] - rm0[tid]) * s0 + be0[tid]);
            float s1 = fold_scale(g1[tid], rv1[tid]);
            g_fold[13824 + tid] = __float_as_uint((b1[tid] - rm1[tid]) * s1 + be1[tid]);
        }
        if (tid < 128) {
            float s2 = fold_scale(g2[tid], rv2[tid]);
            g_fold[13888 + tid] = __float_as_uint((b2[tid] - rm2[tid]) * s2 + be2[tid]);
        }
        // W1 [64][64] -> W1H @0, W1L @2304 (pitch 36 words)
        for (int e = tid; e < 2048; e += 256) {
            int o = e >> 5, c2 = e & 31, c = 2 * c2;
            float s = fold_scale(g1[o], rv1[o]);
            uint32_t hw, lw;
            split2(w1[o * 64 + c] * s, w1[o * 64 + c + 1] * s, hw, lw);
            g_fold[o * 36 + c2]        = hw;
            g_fold[2304 + o * 36 + c2] = lw;
        }
        // W2 [128][64] -> W2H @4608, W2L @9216
        for (int e = tid; e < 4096; e += 256) {
            int o = e >> 5, c2 = e & 31, c = 2 * c2;
            float s = fold_scale(g2[o], rv2[o]);
            uint32_t hw, lw;
            split2(w2[o * 64 + c] * s, w2[o * 64 + c + 1] * s, hw, lw);
            g_fold[4608 + o * 36 + c2] = hw;
            g_fold[9216 + o * 36 + c2] = lw;
        }
        return;
    }

    // ---- pack for this block's 64 points ----
    int jbase = blockIdx.x * 64;
    if (tid < 64) {
        int i = jbase + tid;
        float x = xyz[3 * i + 0];
        float y = xyz[3 * i + 1];
        float z = xyz[3 * i + 2];
        float sq = fmaf(z, z, fmaf(y, y, __fmul_rn(x, x)));
        g_pack[i] = make_float4(x, y, z, sq);
    }

    // ---- p0 ----
    for (int e = tid; e < 4096; e += 256) {
        int o = e & 63, c = e >> 6;
        float s = fold_scale(g0[o], rv0[o]);
        w0f[c][o] = w0[o * 67 + 3 + c] * s;
    }
    __syncthreads();

    int o  = tid & 63;
    int jl = tid >> 6;
#pragma unroll 1
    for (int t = 0; t < 16; t++) {
        int j = jbase + jl + (t << 2);
        const float4* prow = (const float4*)(points + (size_t)j * 64);
        float acc = 0.0f;
#pragma unroll
        for (int c4 = 0; c4 < 16; c4++) {
            float4 p = prow[c4];
            acc = fmaf(p.x, w0f[c4 * 4 + 0][o], acc);
            acc = fmaf(p.y, w0f[c4 * 4 + 1][o], acc);
            acc = fmaf(p.z, w0f[c4 * 4 + 2][o], acc);
            acc = fmaf(p.w, w0f[c4 * 4 + 3][o], acc);
        }
        g_P0[(size_t)j * 64 + o] = acc;
    }
}

// ---------------- kernel 2: tau — warp/query, 16th min of first 512 ----
__global__ void __launch_bounds__(128) tau_kernel() {
    int tid = threadIdx.x, wid = tid >> 5, lane = tid & 31;
    int q = blockIdx.x * 4 + wid;
    int base = (q >> 12) << 12;
    const float4* __restrict__ cand = g_pack + base;

    float4 me = g_pack[q];
    float qx = me.x, qy = me.y, qz = me.z, qsq = me.w;

    float d[16];
#pragma unroll
    for (int i = 0; i < 16; i++)
        d[i] = dist2f(qx, qy, qz, qsq, cand[i * 32 + lane]);

    float tau = CUDART_INF_F;
#pragma unroll 1
    for (int it = 0; it < 16; it++) {
        float m = d[0];
#pragma unroll
        for (int i = 1; i < 16; i++) m = fminf(m, d[i]);
#pragma unroll
        for (int off = 16; off; off >>= 1)
            m = fminf(m, __shfl_xor_sync(0xFFFFFFFFu, m, off));
#pragma unroll
        for (int i = 0; i < 16; i++)
            if (d[i] == m) d[i] = CUDART_INF_F;
        tau = m;
    }
    if (lane == 0) g_tau[q] = tau;
}

// ---------------- kernel 3: colsel — collect d<=tau then exact top-16 ----------
__global__ void __launch_bounds__(128) colsel_kernel() {
    __shared__ float sd[4][CAP];
    __shared__ int   si[4][CAP];
    __shared__ int   scnt[4];

    int tid = threadIdx.x, wid = tid >> 5, lane = tid & 31;
    int q = blockIdx.x * 4 + wid;
    int base = (q >> 12) << 12;
    const float4* __restrict__ cand = g_pack + base;

    float4 me = g_pack[q];
    float qx = me.x, qy = me.y, qz = me.z, qsq = me.w;
    float tau = g_tau[q];

    if (lane == 0) scnt[wid] = 0;
    __syncwarp();

#pragma unroll 4
    for (int i = 0; i < 128; i++) {
        int c = i * 32 + lane;
        float dd = dist2f(qx, qy, qz, qsq, cand[c]);
        if (dd <= tau) {
            int pos = atomicAdd(&scnt[wid], 1);
            if (pos < CAP) { sd[wid][pos] = dd; si[wid][pos] = base + c; }
        }
    }
    __syncwarp();

    int cnt = scnt[wid];
    if (cnt > CAP) cnt = CAP;

    // 64-bit keys (monotone dist | idx): exact top_k tie-break semantics
    unsigned long long key[CAP / 32];
#pragma unroll
    for (int g2 = 0; g2 < CAP / 32; g2++) {
        key[g2] = ~0ull;
        int e = lane + (g2 << 5);
        if (e < cnt) {
            unsigned u = __float_as_uint(sd[wid][e]);
            u = ((int)u < 0) ? ~u : (u | 0x80000000u);
            key[g2] = ((unsigned long long)u << 32) | (unsigned)si[wid][e];
        }
    }

#pragma unroll 1
    for (int it = 0; it < KNN; it++) {
        unsigned long long m = key[0];
#pragma unroll
        for (int i = 1; i < CAP / 32; i++) m = (key[i] < m) ? key[i] : m;
#pragma unroll
        for (int off = 16; off; off >>= 1) {
            unsigned long long o = __shfl_xor_sync(0xFFFFFFFFu, m, off);
            m = (o < m) ? o : m;
        }
#pragma unroll
        for (int i = 0; i < CAP / 32; i++)
            if (key[i] == m) key[i] = ~0ull;
        if (lane == 0) g_idx[q * KNN + it] = (int)(m & 0xFFFFFFFFu);
    }
}

// ---------------- kernel 4: fused MLP via mma.sync, phased weights ----------
// smem words: HHI[128*36] @0, HLO @4608, W @9216 (phase1: W1H/W1L; phase2: W2H/W2L),
//             B1 @18432, B2 @18496. Total 18624 words = 74496 B -> 3 CTAs/SM.
#define SW_HHI 0
#define SW_HLO 4608
#define SW_W   9216
#define SW_B1  18432
#define SW_B2  18496
#define MLPMMA_SMEM (18624 * 4)

__global__ void __launch_bounds__(128) mlp_mma_kernel(float* __restrict__ out) {
    extern __shared__ __align__(16) uint32_t smw[];
    float* smf = (float*)smw;
    int tid = threadIdx.x;

    // phase-1 copy: W1 (4608 words) + biases (192 words)
    // NOTE: block has 128 threads -> biases MUST be a strided loop (R13 bug:
    // `if (tid < 192)` left B2[64..127] uninitialized).
    {
        uint4* dst = (uint4*)(smw + SW_W);
        const uint4* src = (const uint4*)g_fold;
        for (int e = tid; e < 1152; e += 128) dst[e] = src[e];
        for (int e = tid; e < 192; e += 128) smw[SW_B1 + e] = g_fold[13824 + e];
    }

    // ---- layer 0 (scalar) -> H0 hi/lo in smem ----
    int row = blockIdx.x * 128 + tid;
    int q   = row >> 4;
    int j   = g_idx[row];

    float4 pj = g_pack[j];
    float4 pq = g_pack[q];
    float rx = pj.x - pq.x, ry = pj.y - pq.y, rz = pj.z - pq.z;

    const float4* p0row = (const float4*)(g_P0 + (size_t)j * 64);
#pragma unroll
    for (int o4 = 0; o4 < 16; o4++) {
        float4 p = p0row[o4];
        float pv[4] = { p.x, p.y, p.z, p.w };
        float hv[4];
#pragma unroll
        for (int u = 0; u < 4; u++) {
            float4 w = g_W0Bd[o4 * 4 + u];
            float v = fmaf(w.x, rx, fmaf(w.y, ry, fmaf(w.z, rz, pv[u] + w.w)));
            hv[u] = fmaxf(v, 0.0f);
        }
        uint32_t hw, lw;
        split2(hv[0], hv[1], hw, lw);
        smw[SW_HHI + tid * 36 + o4 * 2]     = hw;
        smw[SW_HLO + tid * 36 + o4 * 2]     = lw;
        split2(hv[2], hv[3], hw, lw);
        smw[SW_HHI + tid * 36 + o4 * 2 + 1] = hw;
        smw[SW_HLO + tid * 36 + o4 * 2 + 1] = lw;
    }
    __syncthreads();

    int w    = tid >> 5;
    int lane = tid & 31;
    int g    = lane >> 2;
    int t    = lane & 3;
    int m0   = w * 32;

    // A fragments
    uint32_t Ah[2][4][4], Al[2][4][4];
#pragma unroll
    for (int mt = 0; mt < 2; mt++) {
        int r0 = (m0 + mt * 16 + g) * 36;
        int r1 = r0 + 8 * 36;
#pragma unroll
        for (int kt = 0; kt < 4; kt++) {
            int cw = kt * 8 + t;
            Ah[mt][kt][0] = smw[SW_HHI + r0 + cw];
            Ah[mt][kt][1] = smw[SW_HHI + r1 + cw];
            Ah[mt][kt][2] = smw[SW_HHI + r0 + cw + 4];
            Ah[mt][kt][3] = smw[SW_HHI + r1 + cw + 4];
            Al[mt][kt][0] = smw[SW_HLO + r0 + cw];
            Al[mt][kt][1] = smw[SW_HLO + r1 + cw];
            Al[mt][kt][2] = smw[SW_HLO + r0 + cw + 4];
            Al[mt][kt][3] = smw[SW_HLO + r1 + cw + 4];
        }
    }

    // ---- layer 1 (W1H @ SW_W, W1L @ SW_W+2304) ----
#pragma unroll 1
    for (int np = 0; np < 4; np++) {
        float acc[2][2][4];
#pragma unroll
        for (int mt = 0; mt < 2; mt++)
#pragma unroll
            for (int nn = 0; nn < 2; nn++)
#pragma unroll
                for (int i = 0; i < 4; i++) acc[mt][nn][i] = 0.0f;

#pragma unroll
        for (int kt = 0; kt < 4; kt++) {
#pragma unroll
            for (int nn = 0; nn < 2; nn++) {
                int n0 = (np * 2 + nn) * 8;
                int bw = (n0 + g) * 36 + kt * 8 + t;
                uint32_t bh0 = smw[SW_W + bw],        bh1 = smw[SW_W + bw + 4];
                uint32_t bl0 = smw[SW_W + 2304 + bw], bl1 = smw[SW_W + 2304 + bw + 4];
#pragma unroll
                for (int mt = 0; mt < 2; mt++) {
                    mma16816(acc[mt][nn], Ah[mt][kt], bh0, bh1);
                    mma16816(acc[mt][nn], Ah[mt][kt], bl0, bl1);
                    mma16816(acc[mt][nn], Al[mt][kt], bh0, bh1);
                }
            }
        }
#pragma unroll
        for (int nn = 0; nn < 2; nn++) {
            int n0 = (np * 2 + nn) * 8;
            float bias0 = smf[SW_B1 + n0 + 2 * t];
            float bias1 = smf[SW_B1 + n0 + 2 * t + 1];
#pragma unroll
            for (int mt = 0; mt < 2; mt++) {
                int r0 = (m0 + mt * 16 + g) * 36;
                int cw = n0 / 2 + t;
                float v0 = fmaxf(acc[mt][nn][0] + bias0, 0.0f);
                float v1 = fmaxf(acc[mt][nn][1] + bias1, 0.0f);
                float v2 = fmaxf(acc[mt][nn][2] + bias0, 0.0f);
                float v3 = fmaxf(acc[mt][nn][3] + bias1, 0.0f);
                uint32_t hw, lw;
                split2(v0, v1, hw, lw);
                smw[SW_HHI + r0 + cw] = hw;
                smw[SW_HLO + r0 + cw] = lw;
                split2(v2, v3, hw, lw);
                smw[SW_HHI + r0 + 288 + cw] = hw;
                smw[SW_HLO + r0 + 288 + cw] = lw;
            }
        }
    }

    // ---- phase-2: swap W1 -> W2 in smem ----
    __syncthreads();
    {
        uint4* dst = (uint4*)(smw + SW_W);
        const uint4* src = (const uint4*)g_fold + 1152;   // word 4608
        for (int e = tid; e < 2304; e += 128) dst[e] = src[e];
    }
    __syncthreads();

    // reload A fragments (now h1)
#pragma unroll
    for (int mt = 0; mt < 2; mt++) {
        int r0 = (m0 + mt * 16 + g) * 36;
        int r1 = r0 + 8 * 36;
#pragma unroll
        for (int kt = 0; kt < 4; kt++) {
            int cw = kt * 8 + t;
            Ah[mt][kt][0] = smw[SW_HHI + r0 + cw];
            Ah[mt][kt][1] = smw[SW_HHI + r1 + cw];
            Ah[mt][kt][2] = smw[SW_HHI + r0 + cw + 4];
            Ah[mt][kt][3] = smw[SW_HHI + r1 + cw + 4];
            Al[mt][kt][0] = smw[SW_HLO + r0 + cw];
            Al[mt][kt][1] = smw[SW_HLO + r1 + cw];
            Al[mt][kt][2] = smw[SW_HLO + r0 + cw + 4];
            Al[mt][kt][3] = smw[SW_HLO + r1 + cw + 4];
        }
    }

    // ---- layer 2 (W2H @ SW_W, W2L @ SW_W+4608) + maxpool ----
#pragma unroll 1
    for (int np = 0; np < 8; np++) {
        float acc[2][2][4];
#pragma unroll
        for (int mt = 0; mt < 2; mt++)
#pragma unroll
            for (int nn = 0; nn < 2; nn++)
#pragma unroll
                for (int i = 0; i < 4; i++) acc[mt][nn][i] = 0.0f;

#pragma unroll
        for (int kt = 0; kt < 4; kt++) {
#pragma unroll
            for (int nn = 0; nn < 2; nn++) {
                int n0 = (np * 2 + nn) * 8;
                int bw = (n0 + g) * 36 + kt * 8 + t;
                uint32_t bh0 = smw[SW_W + bw],        bh1 = smw[SW_W + bw + 4];
                uint32_t bl0 = smw[SW_W + 4608 + bw], bl1 = smw[SW_W + 4608 + bw + 4];
#pragma unroll
                for (int mt = 0; mt < 2; mt++) {
                    mma16816(acc[mt][nn], Ah[mt][kt], bh0, bh1);
                    mma16816(acc[mt][nn], Ah[mt][kt], bl0, bl1);
                    mma16816(acc[mt][nn], Al[mt][kt], bh0, bh1);
                }
            }
        }
#pragma unroll
        for (int nn = 0; nn < 2; nn++) {
            int n0 = (np * 2 + nn) * 8;
            float bias0 = smf[SW_B2 + n0 + 2 * t];
            float bias1 = smf[SW_B2 + n0 + 2 * t + 1];
#pragma unroll
            for (int mt = 0; mt < 2; mt++) {
                float m01 = fmaxf(fmaxf(acc[mt][nn][0] + bias0, 0.0f),
                                  fmaxf(acc[mt][nn][2] + bias0, 0.0f));
                float m23 = fmaxf(fmaxf(acc[mt][nn][1] + bias1, 0.0f),
                                  fmaxf(acc[mt][nn][3] + bias1, 0.0f));
#pragma unroll
                for (int off = 4; off <= 16; off <<= 1) {
                    m01 = fmaxf(m01, __shfl_xor_sync(0xFFFFFFFFu, m01, off));
                    m23 = fmaxf(m23, __shfl_xor_sync(0xFFFFFFFFu, m23, off));
                }
                if (g == 0) {
                    int qq = blockIdx.x * 8 + w * 2 + mt;
                    out[(size_t)qq * C2 + n0 + 2 * t]     = m01;
                    out[(size_t)qq * C2 + n0 + 2 * t + 1] = m23;
                }
            }
        }
    }
}

// ---------------- launch ----------------
extern "C" void kernel_launch(void* const* d_in, const int* in_sizes, int n_in,
                              void* d_out, int out_size) {
    (void)in_sizes; (void)n_in; (void)out_size;
    const float* xyz    = (const float*)d_in[0];
    const float* points = (const float*)d_in[1];
    const float* w0  = (const float*)d_in[2];
    const float* b0  = (const float*)d_in[3];
    const float* g0  = (const float*)d_in[4];
    const float* be0 = (const float*)d_in[5];
    const float* rm0 = (const float*)d_in[6];
    const float* rv0 = (const float*)d_in[7];
    const float* w1  = (const float*)d_in[8];
    const float* b1  = (const float*)d_in[9];
    const float* g1  = (const float*)d_in[10];
    const float* be1 = (const float*)d_in[11];
    const float* rm1 = (const float*)d_in[12];
    const float* rv1 = (const float*)d_in[13];
    const float* w2  = (const float*)d_in[14];
    const float* b2  = (const float*)d_in[15];
    const float* g2  = (const float*)d_in[16];
    const float* be2 = (const float*)d_in[17];
    const float* rm2 = (const float*)d_in[18];
    const float* rv2 = (const float*)d_in[19];
    float* out = (float*)d_out;

    cudaFuncSetAttribute(mlp_mma_kernel,
                         cudaFuncAttributeMaxDynamicSharedMemorySize, MLPMMA_SMEM);

    prep_kernel<<<257, 256>>>(xyz, points,
                              w0, b0, g0, be0, rm0, rv0,
                              w1, b1, g1, be1, rm1, rv1,
                              w2, b2, g2, be2, rm2, rv2);
    tau_kernel<<<NQ / 4, 128>>>();
    colsel_kernel<<<NQ / 4, 128>>>();
    mlp_mma_kernel<<<NROWS / 128, 128, MLPMMA_SMEM>>>(out);
}

// round 16
// speedup vs baseline: 2.5872x; 1.0758x over previous
#include <cuda_runtime.h>
#include <cuda_bf16.h>
#include <math_constants.h>
#include <cstdint>

#define BATCH  4
#define NPTS   4096
#define NQ     (BATCH * NPTS)   // 16384
#define KNN    16
#define NROWS  (NQ * KNN)       // 262144
#define C2     128
#define EPSBN  1e-5f
#define CAP    384              // survivor cap per query (+8 sigma)

// ---------------- scratch (no device allocations allowed) ----------------
__device__ float4 g_pack[NQ];
__device__ int    g_idx[NROWS];
__device__ float  g_P0[NQ * 64];
__device__ float  g_tau[NQ];
// folded weights: W1H(2304w) W1L(2304w) W2H(4608w) W2L(4608w) B1(64w) B2(128w)
__device__ __align__(16) uint32_t g_fold[14016];
__device__ float4 g_W0Bd[64];

// ---------------- helpers ----------------
__device__ __forceinline__ float fold_scale(float g, float rv) {
    float v = rv + EPSBN;
    float r = rsqrtf(v);
    r = r * (1.5f - 0.5f * v * r * r);
    return g * r;
}

__device__ __forceinline__ float dist2f(float qx, float qy, float qz, float qsq, float4 p) {
    float dot = fmaf(qz, p.z, fmaf(qy, p.y, __fmul_rn(qx, p.x)));
    return __fadd_rn(__fadd_rn(qsq, p.w), __fmul_rn(-2.0f, dot));
}

// hi/lo bf16 split of two floats
__device__ __forceinline__ void split2(float v0, float v1, uint32_t& hiw, uint32_t& low) {
    __nv_bfloat16 h0 = __float2bfloat16(v0);
    __nv_bfloat16 h1 = __float2bfloat16(v1);
    __nv_bfloat16 l0 = __float2bfloat16(v0 - __bfloat162float(h0));
    __nv_bfloat16 l1 = __float2bfloat16(v1 - __bfloat162float(h1));
    __nv_bfloat162 hp; hp.x = h0; hp.y = h1;
    __nv_bfloat162 lp; lp.x = l0; lp.y = l1;
    hiw = *(uint32_t*)&hp;
    low = *(uint32_t*)&lp;
}

// warp-level bf16 MMA, fp32 accum
__device__ __forceinline__ void mma16816(float* d, const uint32_t* a,
                                         uint32_t b0, uint32_t b1) {
    asm volatile(
        "mma.sync.aligned.m16n8k16.row.col.f32.bf16.bf16.f32 "
        "{%0,%1,%2,%3}, {%4,%5,%6,%7}, {%8,%9}, {%0,%1,%2,%3};"
        : "+f"(d[0]), "+f"(d[1]), "+f"(d[2]), "+f"(d[3])
        : "r"(a[0]), "r"(a[1]), "r"(a[2]), "r"(a[3]), "r"(b0), "r"(b1));
}

// ---------------- kernel 1: prep = pack + p0 + foldw ----------------
__global__ void __launch_bounds__(256) prep_kernel(
    const float* __restrict__ xyz, const float* __restrict__ points,
    const float* __restrict__ w0, const float* __restrict__ b0,
    const float* __restrict__ g0, const float* __restrict__ be0,
    const float* __restrict__ rm0, const float* __restrict__ rv0,
    const float* __restrict__ w1, const float* __restrict__ b1,
    const float* __restrict__ g1, const float* __restrict__ be1,
    const float* __restrict__ rm1, const float* __restrict__ rv1,
    const float* __restrict__ w2, const float* __restrict__ b2,
    const float* __restrict__ g2, const float* __restrict__ be2,
    const float* __restrict__ rm2, const float* __restrict__ rv2)
{
    __shared__ float w0f[64][64];
    int tid = threadIdx.x;

    if (blockIdx.x == 256) {
        // ---- foldw ----
        if (tid < 64) {
            float s0 = fold_scale(g0[tid], rv0[tid]);
            g_W0Bd[tid] = make_float4(w0[tid * 67 + 0] * s0,
                                      w0[tid * 67 + 1] * s0,
                                      w0[tid * 67 + 2] * s0,
                                      (b0[tid] - rm0[tid]) * s0 + be0[tid]);
            float s1 = fold_scale(g1[tid], rv1[tid]);
            g_fold[13824 + tid] = __float_as_uint((b1[tid] - rm1[tid]) * s1 + be1[tid]);
        }
        if (tid < 128) {
            float s2 = fold_scale(g2[tid], rv2[tid]);
            g_fold[13888 + tid] = __float_as_uint((b2[tid] - rm2[tid]) * s2 + be2[tid]);
        }
        // W1 [64][64] -> W1H @0, W1L @2304 (pitch 36 words)
        for (int e = tid; e < 2048; e += 256) {
            int o = e >> 5, c2 = e & 31, c = 2 * c2;
            float s = fold_scale(g1[o], rv1[o]);
            uint32_t hw, lw;
            split2(w1[o * 64 + c] * s, w1[o * 64 + c + 1] * s, hw, lw);
            g_fold[o * 36 + c2]        = hw;
            g_fold[2304 + o * 36 + c2] = lw;
        }
        // W2 [128][64] -> W2H @4608, W2L @9216
        for (int e = tid; e < 4096; e += 256) {
            int o = e >> 5, c2 = e & 31, c = 2 * c2;
            float s = fold_scale(g2[o], rv2[o]);
            uint32_t hw, lw;
            split2(w2[o * 64 + c] * s, w2[o * 64 + c + 1] * s, hw, lw);
            g_fold[4608 + o * 36 + c2] = hw;
            g_fold[9216 + o * 36 + c2] = lw;
        }
        return;
    }

    // ---- pack for this block's 64 points ----
    int jbase = blockIdx.x * 64;
    if (tid < 64) {
        int i = jbase + tid;
        float x = xyz[3 * i + 0];
        float y = xyz[3 * i + 1];
        float z = xyz[3 * i + 2];
        float sq = fmaf(z, z, fmaf(y, y, __fmul_rn(x, x)));
        g_pack[i] = make_float4(x, y, z, sq);
    }

    // ---- p0 ----
    for (int e = tid; e < 4096; e += 256) {
        int o = e & 63, c = e >> 6;
        float s = fold_scale(g0[o], rv0[o]);
        w0f[c][o] = w0[o * 67 + 3 + c] * s;
    }
    __syncthreads();

    int o  = tid & 63;
    int jl = tid >> 6;
#pragma unroll 1
    for (int t = 0; t < 16; t++) {
        int j = jbase + jl + (t << 2);
        const float4* prow = (const float4*)(points + (size_t)j * 64);
        float acc = 0.0f;
#pragma unroll
        for (int c4 = 0; c4 < 16; c4++) {
            float4 p = prow[c4];
            acc = fmaf(p.x, w0f[c4 * 4 + 0][o], acc);
            acc = fmaf(p.y, w0f[c4 * 4 + 1][o], acc);
            acc = fmaf(p.z, w0f[c4 * 4 + 2][o], acc);
            acc = fmaf(p.w, w0f[c4 * 4 + 3][o], acc);
        }
        g_P0[(size_t)j * 64 + o] = acc;
    }
}

// ---------------- kernel 2: tau — warp/query, 16th min of first 512 ----
__global__ void __launch_bounds__(128) tau_kernel() {
    int tid = threadIdx.x, wid = tid >> 5, lane = tid & 31;
    int q = blockIdx.x * 4 + wid;
    int base = (q >> 12) << 12;
    const float4* __restrict__ cand = g_pack + base;

    float4 me = g_pack[q];
    float qx = me.x, qy = me.y, qz = me.z, qsq = me.w;

    float d[16];
#pragma unroll
    for (int i = 0; i < 16; i++)
        d[i] = dist2f(qx, qy, qz, qsq, cand[i * 32 + lane]);

    float tau = CUDART_INF_F;
#pragma unroll 1
    for (int it = 0; it < 16; it++) {
        float m = d[0];
#pragma unroll
        for (int i = 1; i < 16; i++) m = fminf(m, d[i]);
#pragma unroll
        for (int off = 16; off; off >>= 1)
            m = fminf(m, __shfl_xor_sync(0xFFFFFFFFu, m, off));
#pragma unroll
        for (int i = 0; i < 16; i++)
            if (d[i] == m) d[i] = CUDART_INF_F;
        tau = m;
    }
    if (lane == 0) g_tau[q] = tau;
}

// ---------------- kernel 3: colsel — collect d<=tau then exact top-16 ----------
__global__ void __launch_bounds__(128) colsel_kernel() {
    __shared__ float sd[4][CAP];
    __shared__ int   si[4][CAP];
    __shared__ int   scnt[4];

    int tid = threadIdx.x, wid = tid >> 5, lane = tid & 31;
    int q = blockIdx.x * 4 + wid;
    int base = (q >> 12) << 12;
    const float4* __restrict__ cand = g_pack + base;

    float4 me = g_pack[q];
    float qx = me.x, qy = me.y, qz = me.z, qsq = me.w;
    float tau = g_tau[q];

    if (lane == 0) scnt[wid] = 0;
    __syncwarp();

#pragma unroll 4
    for (int i = 0; i < 128; i++) {
        int c = i * 32 + lane;
        float dd = dist2f(qx, qy, qz, qsq, cand[c]);
        if (dd <= tau) {
            int pos = atomicAdd(&scnt[wid], 1);
            if (pos < CAP) { sd[wid][pos] = dd; si[wid][pos] = base + c; }
        }
    }
    __syncwarp();

    int cnt = scnt[wid];
    if (cnt > CAP) cnt = CAP;

    // 64-bit keys (monotone dist | idx): exact top_k tie-break semantics
    unsigned long long key[CAP / 32];
#pragma unroll
    for (int g2 = 0; g2 < CAP / 32; g2++) {
        key[g2] = ~0ull;
        int e = lane + (g2 << 5);
        if (e < cnt) {
            unsigned u = __float_as_uint(sd[wid][e]);
            u = ((int)u < 0) ? ~u : (u | 0x80000000u);
            key[g2] = ((unsigned long long)u << 32) | (unsigned)si[wid][e];
        }
    }

#pragma unroll 1
    for (int it = 0; it < KNN; it++) {
        unsigned long long m = key[0];
#pragma unroll
        for (int i = 1; i < CAP / 32; i++) m = (key[i] < m) ? key[i] : m;
#pragma unroll
        for (int off = 16; off; off >>= 1) {
            unsigned long long o = __shfl_xor_sync(0xFFFFFFFFu, m, off);
            m = (o < m) ? o : m;
        }
#pragma unroll
        for (int i = 0; i < CAP / 32; i++)
            if (key[i] == m) key[i] = ~0ull;
        if (lane == 0) g_idx[q * KNN + it] = (int)(m & 0xFFFFFFFFu);
    }
}

// ---------------- kernel 4: fused MLP via mma.sync, 256 rows/CTA -------------
// smem words: HHI[256*36] @0, HLO @9216, W @18432 (phase1 W1H/W1L; phase2 W2H/W2L),
//             B1 @27648, B2 @27712. Total 27840 words = 111.4KB -> 2 CTAs/SM,
//             16 warps/SM (was 12). __launch_bounds__(256,2) caps regs at 128.
#define SW_HHI 0
#define SW_HLO 9216
#define SW_W   18432
#define SW_B1  27648
#define SW_B2  27712
#define MLPMMA_SMEM (27840 * 4)

__global__ void __launch_bounds__(256, 2) mlp_mma_kernel(float* __restrict__ out) {
    extern __shared__ __align__(16) uint32_t smw[];
    float* smf = (float*)smw;
    int tid = threadIdx.x;

    // phase-1 copy: W1 (4608 words) + biases (192 words, strided loop!)
    {
        uint4* dst = (uint4*)(smw + SW_W);
        const uint4* src = (const uint4*)g_fold;
        for (int e = tid; e < 1152; e += 256) dst[e] = src[e];
        for (int e = tid; e < 192; e += 256) smw[SW_B1 + e] = g_fold[13824 + e];
    }

    // ---- layer 0 (scalar) -> H0 hi/lo in smem ----
    int row = blockIdx.x * 256 + tid;
    int q   = row >> 4;
    int j   = g_idx[row];

    float4 pj = g_pack[j];
    float4 pq = g_pack[q];
    float rx = pj.x - pq.x, ry = pj.y - pq.y, rz = pj.z - pq.z;

    const float4* p0row = (const float4*)(g_P0 + (size_t)j * 64);
#pragma unroll
    for (int o4 = 0; o4 < 16; o4++) {
        float4 p = p0row[o4];
        float pv[4] = { p.x, p.y, p.z, p.w };
        float hv[4];
#pragma unroll
        for (int u = 0; u < 4; u++) {
            float4 w = g_W0Bd[o4 * 4 + u];
            float v = fmaf(w.x, rx, fmaf(w.y, ry, fmaf(w.z, rz, pv[u] + w.w)));
            hv[u] = fmaxf(v, 0.0f);
        }
        uint32_t hw, lw;
        split2(hv[0], hv[1], hw, lw);
        smw[SW_HHI + tid * 36 + o4 * 2]     = hw;
        smw[SW_HLO + tid * 36 + o4 * 2]     = lw;
        split2(hv[2], hv[3], hw, lw);
        smw[SW_HHI + tid * 36 + o4 * 2 + 1] = hw;
        smw[SW_HLO + tid * 36 + o4 * 2 + 1] = lw;
    }
    __syncthreads();

    int w    = tid >> 5;          // 0..7
    int lane = tid & 31;
    int g    = lane >> 2;
    int t    = lane & 3;
    int m0   = w * 32;

    // A fragments
    uint32_t Ah[2][4][4], Al[2][4][4];
#pragma unroll
    for (int mt = 0; mt < 2; mt++) {
        int r0 = (m0 + mt * 16 + g) * 36;
        int r1 = r0 + 8 * 36;
#pragma unroll
        for (int kt = 0; kt < 4; kt++) {
            int cw = kt * 8 + t;
            Ah[mt][kt][0] = smw[SW_HHI + r0 + cw];
            Ah[mt][kt][1] = smw[SW_HHI + r1 + cw];
            Ah[mt][kt][2] = smw[SW_HHI + r0 + cw + 4];
            Ah[mt][kt][3] = smw[SW_HHI + r1 + cw + 4];
            Al[mt][kt][0] = smw[SW_HLO + r0 + cw];
            Al[mt][kt][1] = smw[SW_HLO + r1 + cw];
            Al[mt][kt][2] = smw[SW_HLO + r0 + cw + 4];
            Al[mt][kt][3] = smw[SW_HLO + r1 + cw + 4];
        }
    }

    // ---- layer 1 (W1H @ SW_W, W1L @ SW_W+2304) ----
#pragma unroll 1
    for (int np = 0; np < 4; np++) {
        float acc[2][2][4];
#pragma unroll
        for (int mt = 0; mt < 2; mt++)
#pragma unroll
            for (int nn = 0; nn < 2; nn++)
#pragma unroll
                for (int i = 0; i < 4; i++) acc[mt][nn][i] = 0.0f;

#pragma unroll
        for (int kt = 0; kt < 4; kt++) {
#pragma unroll
            for (int nn = 0; nn < 2; nn++) {
                int n0 = (np * 2 + nn) * 8;
                int bw = (n0 + g) * 36 + kt * 8 + t;
                uint32_t bh0 = smw[SW_W + bw],        bh1 = smw[SW_W + bw + 4];
                uint32_t bl0 = smw[SW_W + 2304 + bw], bl1 = smw[SW_W + 2304 + bw + 4];
#pragma unroll
                for (int mt = 0; mt < 2; mt++) {
                    mma16816(acc[mt][nn], Ah[mt][kt], bh0, bh1);
                    mma16816(acc[mt][nn], Ah[mt][kt], bl0, bl1);
                    mma16816(acc[mt][nn], Al[mt][kt], bh0, bh1);
                }
            }
        }
#pragma unroll
        for (int nn = 0; nn < 2; nn++) {
            int n0 = (np * 2 + nn) * 8;
            float bias0 = smf[SW_B1 + n0 + 2 * t];
            float bias1 = smf[SW_B1 + n0 + 2 * t + 1];
#pragma unroll
            for (int mt = 0; mt < 2; mt++) {
                int r0 = (m0 + mt * 16 + g) * 36;
                int cw = n0 / 2 + t;
                float v0 = fmaxf(acc[mt][nn][0] + bias0, 0.0f);
                float v1 = fmaxf(acc[mt][nn][1] + bias1, 0.0f);
                float v2 = fmaxf(acc[mt][nn][2] + bias0, 0.0f);
                float v3 = fmaxf(acc[mt][nn][3] + bias1, 0.0f);
                uint32_t hw, lw;
                split2(v0, v1, hw, lw);
                smw[SW_HHI + r0 + cw] = hw;
                smw[SW_HLO + r0 + cw] = lw;
                split2(v2, v3, hw, lw);
                smw[SW_HHI + r0 + 288 + cw] = hw;
                smw[SW_HLO + r0 + 288 + cw] = lw;
            }
        }
    }

    // ---- phase-2: swap W1 -> W2 in smem ----
    __syncthreads();
    {
        uint4* dst = (uint4*)(smw + SW_W);
        const uint4* src = (const uint4*)g_fold + 1152;   // word 4608
        for (int e = tid; e < 2304; e += 256) dst[e] = src[e];
    }
    __syncthreads();

    // reload A fragments (now h1)
#pragma unroll
    for (int mt = 0; mt < 2; mt++) {
        int r0 = (m0 + mt * 16 + g) * 36;
        int r1 = r0 + 8 * 36;
#pragma unroll
        for (int kt = 0; kt < 4; kt++) {
            int cw = kt * 8 + t;
            Ah[mt][kt][0] = smw[SW_HHI + r0 + cw];
            Ah[mt][kt][1] = smw[SW_HHI + r1 + cw];
            Ah[mt][kt][2] = smw[SW_HHI + r0 + cw + 4];
            Ah[mt][kt][3] = smw[SW_HHI + r1 + cw + 4];
            Al[mt][kt][0] = smw[SW_HLO + r0 + cw];
            Al[mt][kt][1] = smw[SW_HLO + r1 + cw];
            Al[mt][kt][2] = smw[SW_HLO + r0 + cw + 4];
            Al[mt][kt][3] = smw[SW_HLO + r1 + cw + 4];
        }
    }

    // ---- layer 2 (W2H @ SW_W, W2L @ SW_W+4608) + maxpool ----
#pragma unroll 1
    for (int np = 0; np < 8; np++) {
        float acc[2][2][4];
#pragma unroll
        for (int mt = 0; mt < 2; mt++)
#pragma unroll
            for (int nn = 0; nn < 2; nn++)
#pragma unroll
                for (int i = 0; i < 4; i++) acc[mt][nn][i] = 0.0f;

#pragma unroll
        for (int kt = 0; kt < 4; kt++) {
#pragma unroll
            for (int nn = 0; nn < 2; nn++) {
                int n0 = (np * 2 + nn) * 8;
                int bw = (n0 + g) * 36 + kt * 8 + t;
                uint32_t bh0 = smw[SW_W + bw],        bh1 = smw[SW_W + bw + 4];
                uint32_t bl0 = smw[SW_W + 4608 + bw], bl1 = smw[SW_W + 4608 + bw + 4];
#pragma unroll
                for (int mt = 0; mt < 2; mt++) {
                    mma16816(acc[mt][nn], Ah[mt][kt], bh0, bh1);
                    mma16816(acc[mt][nn], Ah[mt][kt], bl0, bl1);
                    mma16816(acc[mt][nn], Al[mt][kt], bh0, bh1);
                }
            }
        }
#pragma unroll
        for (int nn = 0; nn < 2; nn++) {
            int n0 = (np * 2 + nn) * 8;
            float bias0 = smf[SW_B2 + n0 + 2 * t];
            float bias1 = smf[SW_B2 + n0 + 2 * t + 1];
#pragma unroll
            for (int mt = 0; mt < 2; mt++) {
                float m01 = fmaxf(fmaxf(acc[mt][nn][0] + bias0, 0.0f),
                                  fmaxf(acc[mt][nn][2] + bias0, 0.0f));
                float m23 = fmaxf(fmaxf(acc[mt][nn][1] + bias1, 0.0f),
                                  fmaxf(acc[mt][nn][3] + bias1, 0.0f));
#pragma unroll
                for (int off = 4; off <= 16; off <<= 1) {
                    m01 = fmaxf(m01, __shfl_xor_sync(0xFFFFFFFFu, m01, off));
                    m23 = fmaxf(m23, __shfl_xor_sync(0xFFFFFFFFu, m23, off));
                }
                if (g == 0) {
                    int qq = blockIdx.x * 16 + w * 2 + mt;
                    out[(size_t)qq * C2 + n0 + 2 * t]     = m01;
                    out[(size_t)qq * C2 + n0 + 2 * t + 1] = m23;
                }
            }
        }
    }
}

// ---------------- launch ----------------
extern "C" void kernel_launch(void* const* d_in, const int* in_sizes, int n_in,
                              void* d_out, int out_size) {
    (void)in_sizes; (void)n_in; (void)out_size;
    const float* xyz    = (const float*)d_in[0];
    const float* points = (const float*)d_in[1];
    const float* w0  = (const float*)d_in[2];
    const float* b0  = (const float*)d_in[3];
    const float* g0  = (const float*)d_in[4];
    const float* be0 = (const float*)d_in[5];
    const float* rm0 = (const float*)d_in[6];
    const float* rv0 = (const float*)d_in[7];
    const float* w1  = (const float*)d_in[8];
    const float* b1  = (const float*)d_in[9];
    const float* g1  = (const float*)d_in[10];
    const float* be1 = (const float*)d_in[11];
    const float* rm1 = (const float*)d_in[12];
    const float* rv1 = (const float*)d_in[13];
    const float* w2  = (const float*)d_in[14];
    const float* b2  = (const float*)d_in[15];
    const float* g2  = (const float*)d_in[16];
    const float* be2 = (const float*)d_in[17];
    const float* rm2 = (const float*)d_in[18];
    const float* rv2 = (const float*)d_in[19];
    float* out = (float*)d_out;

    cudaFuncSetAttribute(mlp_mma_kernel,
                         cudaFuncAttributeMaxDynamicSharedMemorySize, MLPMMA_SMEM);

    prep_kernel<<<257, 256>>>(xyz, points,
                              w0, b0, g0, be0, rm0, rv0,
                              w1, b1, g1, be1, rm1, rv1,
                              w2, b2, g2, be2, rm2, rv2);
    tau_kernel<<<NQ / 4, 128>>>();
    colsel_kernel<<<NQ / 4, 128>>>();
    mlp_mma_kernel<<<NROWS / 256, 256, MLPMMA_SMEM>>>(out);
}